// round 7
// baseline (speedup 1.0000x reference)
#include <cuda_runtime.h>
#include <cuda_bf16.h>
#include <math.h>
#include <stdint.h>

#define Nn 2000
#define Cc 256
#define Hh 8
#define Dd 32
#define LD 2048
#define N3C 768

// ---------------- scratch (static __device__, no allocation) ----------------
__device__ float g_qkv[2][Nn * N3C];             // raw qkv for cls/reg
__device__ float g_v[Hh * Nn * Dd];              // raw v_cls [h][n][d]
__device__ __nv_bfloat16 g_qA[2][Hh * Nn * 128]; // q split, A-side dup [hi,lo,hi,lo]
__device__ __nv_bfloat16 g_kB[2][Hh * Nn * 128]; // k split, B-side dup [hi,hi,lo,lo]
__device__ __nv_bfloat16 g_vnP[Nn * 256];        // vn plain bf16, head-concat [n][h*32+d]
__device__ float g_e[2][Hh][Nn * LD];            // exp(logits) per (p, head), fp32
__device__ float g_attn[Nn * LD];                // sum over heads of masked w
__device__ float g_raw[Nn * LD];                 // sum over heads of vn@vn^T
__device__ float g_S[2][Hh * Nn];                // softmax row sums (fp32)

// ---------------- PTX helpers ----------------
__device__ __forceinline__ uint32_t smem_u32(const void* p) {
    uint32_t r;
    asm("{ .reg .u64 t; cvta.to.shared.u64 t, %1; cvt.u32.u64 %0, t; }" : "=r"(r) : "l"(p));
    return r;
}
#define LDSM4(r, addr) \
    asm volatile("ldmatrix.sync.aligned.m8n8.x4.shared.b16 {%0,%1,%2,%3}, [%4];" \
        : "=r"((r)[0]), "=r"((r)[1]), "=r"((r)[2]), "=r"((r)[3]) : "r"(addr))
#define MMA_BF16(c, a, b0v, b1v) \
    asm volatile("mma.sync.aligned.m16n8k16.row.col.f32.bf16.bf16.f32 " \
        "{%0,%1,%2,%3}, {%4,%5,%6,%7}, {%8,%9}, {%0,%1,%2,%3};" \
        : "+f"((c)[0]), "+f"((c)[1]), "+f"((c)[2]), "+f"((c)[3]) \
        : "r"((a)[0]), "r"((a)[1]), "r"((a)[2]), "r"((a)[3]), "r"(b0v), "r"(b1v))

// ---------------- zero row sums ----------------
__global__ void k_zeroS() {
    int i = blockIdx.x * 256 + threadIdx.x;
    if (i < 2 * Hh * Nn) ((float*)g_S)[i] = 0.f;
}

// ---------------- QKV GEMM: [2000,256] @ [256,768] --------------------------
__global__ __launch_bounds__(256) void k_gemm(const float* __restrict__ xc,
                                              const float* __restrict__ wc,
                                              const float* __restrict__ xr,
                                              const float* __restrict__ wr) {
    __shared__ float sa[32][132];
    __shared__ float sb[32][132];
    int z = blockIdx.z;
    const float* A = z ? xr : xc;
    const float* B = z ? wr : wc;
    float* Cout = g_qkv[z];
    int t = threadIdx.x, ty = t >> 4, tx = t & 15;
    int r0 = blockIdx.y * 128, c0 = blockIdx.x * 128;
    float acc[8][8];
#pragma unroll
    for (int i = 0; i < 8; i++)
#pragma unroll
        for (int j = 0; j < 8; j++) acc[i][j] = 0.f;

    for (int kk0 = 0; kk0 < Cc; kk0 += 32) {
        __syncthreads();
#pragma unroll
        for (int i = 0; i < 4; i++) {
            int idx = t + i * 256;
            int rr = idx >> 3, d4 = (idx & 7) * 4;
            float4 av = make_float4(0.f, 0.f, 0.f, 0.f);
            if (r0 + rr < Nn) av = *reinterpret_cast<const float4*>(&A[(r0 + rr) * Cc + kk0 + d4]);
            sa[d4 + 0][rr] = av.x; sa[d4 + 1][rr] = av.y;
            sa[d4 + 2][rr] = av.z; sa[d4 + 3][rr] = av.w;
        }
#pragma unroll
        for (int i = 0; i < 4; i++) {
            int idx = t + i * 256;
            int rr = idx >> 5, c4 = (idx & 31) * 4;
            float4 bv = *reinterpret_cast<const float4*>(&B[(kk0 + rr) * N3C + c0 + c4]);
            *reinterpret_cast<float4*>(&sb[rr][c4]) = bv;
        }
        __syncthreads();
#pragma unroll
        for (int kk = 0; kk < 32; kk++) {
            float4 a0 = *reinterpret_cast<const float4*>(&sa[kk][ty * 8]);
            float4 a1 = *reinterpret_cast<const float4*>(&sa[kk][ty * 8 + 4]);
            float4 b0 = *reinterpret_cast<const float4*>(&sb[kk][tx * 8]);
            float4 b1 = *reinterpret_cast<const float4*>(&sb[kk][tx * 8 + 4]);
            float a[8] = {a0.x, a0.y, a0.z, a0.w, a1.x, a1.y, a1.z, a1.w};
            float b[8] = {b0.x, b0.y, b0.z, b0.w, b1.x, b1.y, b1.z, b1.w};
#pragma unroll
            for (int i = 0; i < 8; i++)
#pragma unroll
                for (int j = 0; j < 8; j++) acc[i][j] = fmaf(a[i], b[j], acc[i][j]);
        }
    }
#pragma unroll
    for (int i = 0; i < 8; i++) {
        int gr = r0 + ty * 8 + i;
        if (gr < Nn) {
            float* dst = &Cout[gr * N3C + c0 + tx * 8];
            *reinterpret_cast<float4*>(dst) = make_float4(acc[i][0], acc[i][1], acc[i][2], acc[i][3]);
            *reinterpret_cast<float4*>(dst + 4) = make_float4(acc[i][4], acc[i][5], acc[i][6], acc[i][7]);
        }
    }
}

// ---------------- normalize + bf16-split + emit x_ori ----------------------
__device__ __forceinline__ float rnorm_of(float x) {
    float s = x * x;
#pragma unroll
    for (int off = 16; off; off >>= 1) s += __shfl_xor_sync(0xffffffffu, s, off);
    return 1.f / (sqrtf(s) + 1e-8f);
}
__device__ __forceinline__ void split_A(__nv_bfloat16* p, int d, float x) {
    __nv_bfloat16 hi = __float2bfloat16(x);
    __nv_bfloat16 lo = __float2bfloat16(x - __bfloat162float(hi));
    p[d] = hi; p[32 + d] = lo; p[64 + d] = hi; p[96 + d] = lo;
}
__device__ __forceinline__ void split_B(__nv_bfloat16* p, int d, float x) {
    __nv_bfloat16 hi = __float2bfloat16(x);
    __nv_bfloat16 lo = __float2bfloat16(x - __bfloat162float(hi));
    p[d] = hi; p[32 + d] = hi; p[64 + d] = lo; p[96 + d] = lo;
}

__global__ __launch_bounds__(256) void k_norm(float* __restrict__ out) {
    int n = blockIdx.x;
    int h = threadIdx.x >> 5;
    int d = threadIdx.x & 31;
    const float* rc = g_qkv[0] + n * N3C;
    const float* rr = g_qkv[1] + n * N3C;
    float qc = rc[h * Dd + d], kc = rc[Cc + h * Dd + d], vc = rc[2 * Cc + h * Dd + d];
    float qr = rr[h * Dd + d], kr = rr[Cc + h * Dd + d];

    float qcn = qc * rnorm_of(qc), kcn = kc * rnorm_of(kc), vcn = vc * rnorm_of(vc);
    float qrn = qr * rnorm_of(qr), krn = kr * rnorm_of(kr);

    int base = (h * Nn + n) * 128;
    split_A(&g_qA[0][base], d, qcn);
    split_A(&g_qA[1][base], d, qrn);
    split_B(&g_kB[0][base], d, kcn);
    split_B(&g_kB[1][base], d, krn);
    g_vnP[n * 256 + h * Dd + d] = __float2bfloat16(vcn);
    g_v[(h * Nn + n) * Dd + d] = vc;

    out[n * 2 * Cc + h * Dd + d] = 0.f;
    out[n * 2 * Cc + Cc + h * Dd + d] = vc;
}

// ---------------- tensor logits: all heads+p in one launch ------------------
__global__ __launch_bounds__(256) void k_logits_t() {
    extern __shared__ __nv_bfloat16 smbf[];
    __nv_bfloat16* sA = smbf;                 // [128][136]
    __nv_bfloat16* sB = smbf + 128 * 136;
    int t = threadIdx.x, lane = t & 31, wid = t >> 5;
    int wr = wid >> 2, wc = wid & 3;
    int c0 = blockIdx.x * 128, r0 = blockIdx.y * 128;
    int p = blockIdx.z & 1, h = blockIdx.z >> 1;
    const __nv_bfloat16* A = g_qA[p] + h * Nn * 128;
    const __nv_bfloat16* B = g_kB[p] + h * Nn * 128;

#pragma unroll
    for (int i = 0; i < 8; i++) {
        int idx = t + i * 256;
        int row = idx >> 4, c8 = (idx & 15) * 8;
        uint4 va = make_uint4(0, 0, 0, 0), vb = make_uint4(0, 0, 0, 0);
        if (r0 + row < Nn) va = *reinterpret_cast<const uint4*>(A + (r0 + row) * 128 + c8);
        if (c0 + row < Nn) vb = *reinterpret_cast<const uint4*>(B + (c0 + row) * 128 + c8);
        *reinterpret_cast<uint4*>(sA + row * 136 + c8) = va;
        *reinterpret_cast<uint4*>(sB + row * 136 + c8) = vb;
    }
    __syncthreads();

    uint32_t a_base = smem_u32(sA) + ((wr * 64 + (lane & 15)) * 136 + (lane >> 4) * 8) * 2;
    int bn = (lane & 7) + (lane >> 4) * 8;
    uint32_t b_base = smem_u32(sB) + ((wc * 32 + bn) * 136 + ((lane >> 3) & 1) * 8) * 2;

    float acc[4][4][4];
#pragma unroll
    for (int i = 0; i < 4; i++)
#pragma unroll
        for (int j = 0; j < 4; j++)
#pragma unroll
            for (int q = 0; q < 4; q++) acc[i][j][q] = 0.f;

#pragma unroll
    for (int ks = 0; ks < 8; ks++) {
        uint32_t a[4][4], b[2][4];
#pragma unroll
        for (int mt = 0; mt < 4; mt++) LDSM4(a[mt], a_base + (mt * 16 * 136 + ks * 16) * 2);
#pragma unroll
        for (int n2 = 0; n2 < 2; n2++) LDSM4(b[n2], b_base + (n2 * 16 * 136 + ks * 16) * 2);
#pragma unroll
        for (int mt = 0; mt < 4; mt++)
#pragma unroll
            for (int nt = 0; nt < 4; nt++)
                MMA_BF16(acc[mt][nt], a[mt], b[nt >> 1][(nt & 1) * 2], b[nt >> 1][(nt & 1) * 2 + 1]);
    }

    float* E = &g_e[p][h][0];
    float* S = &g_S[p][h * Nn];
    int r_base = r0 + wr * 64 + (lane >> 2);
    int c_base = c0 + wc * 32 + (lane & 3) * 2;
#pragma unroll
    for (int mt = 0; mt < 4; mt++) {
        int r_lo = r_base + mt * 16, r_hi = r_lo + 8;
        float rs_lo = 0.f, rs_hi = 0.f;
#pragma unroll
        for (int nt = 0; nt < 4; nt++) {
            int c = c_base + nt * 8;
            bool cok = (c < Nn);
            float e0 = cok ? __expf(25.f * acc[mt][nt][0] - 25.f) : 0.f;
            float e1 = cok ? __expf(25.f * acc[mt][nt][1] - 25.f) : 0.f;
            float e2 = cok ? __expf(25.f * acc[mt][nt][2] - 25.f) : 0.f;
            float e3 = cok ? __expf(25.f * acc[mt][nt][3] - 25.f) : 0.f;
            rs_lo += e0 + e1;
            rs_hi += e2 + e3;
            if (cok && r_lo < Nn) *reinterpret_cast<float2*>(&E[r_lo * LD + c]) = make_float2(e0, e1);
            if (cok && r_hi < Nn) *reinterpret_cast<float2*>(&E[r_hi * LD + c]) = make_float2(e2, e3);
        }
        rs_lo += __shfl_xor_sync(0xffffffffu, rs_lo, 1);
        rs_lo += __shfl_xor_sync(0xffffffffu, rs_lo, 2);
        rs_hi += __shfl_xor_sync(0xffffffffu, rs_hi, 1);
        rs_hi += __shfl_xor_sync(0xffffffffu, rs_hi, 2);
        if ((lane & 3) == 0) {
            if (r_lo < Nn) atomicAdd(&S[r_lo], rs_lo);
            if (r_hi < Nn) atomicAdd(&S[r_hi], rs_hi);
        }
    }
}

// ---------------- tensor raw: sum over heads of vn@vn^T (K=256 bf16) --------
__global__ __launch_bounds__(256) void k_raw_t() {
    extern __shared__ __nv_bfloat16 smbf[];
    __nv_bfloat16* sA = smbf;
    __nv_bfloat16* sB = smbf + 128 * 136;
    int t = threadIdx.x, lane = t & 31, wid = t >> 5;
    int wr = wid >> 2, wc = wid & 3;
    int c0 = blockIdx.x * 128, r0 = blockIdx.y * 128;

    float acc[4][4][4];
#pragma unroll
    for (int i = 0; i < 4; i++)
#pragma unroll
        for (int j = 0; j < 4; j++)
#pragma unroll
            for (int q = 0; q < 4; q++) acc[i][j][q] = 0.f;

    uint32_t a_base = smem_u32(sA) + ((wr * 64 + (lane & 15)) * 136 + (lane >> 4) * 8) * 2;
    int bn = (lane & 7) + (lane >> 4) * 8;
    uint32_t b_base = smem_u32(sB) + ((wc * 32 + bn) * 136 + ((lane >> 3) & 1) * 8) * 2;

    for (int kc = 0; kc < 2; kc++) {
        __syncthreads();
#pragma unroll
        for (int i = 0; i < 8; i++) {
            int idx = t + i * 256;
            int row = idx >> 4, c8 = (idx & 15) * 8;
            uint4 va = make_uint4(0, 0, 0, 0), vb = make_uint4(0, 0, 0, 0);
            if (r0 + row < Nn) va = *reinterpret_cast<const uint4*>(&g_vnP[(r0 + row) * 256 + kc * 128 + c8]);
            if (c0 + row < Nn) vb = *reinterpret_cast<const uint4*>(&g_vnP[(c0 + row) * 256 + kc * 128 + c8]);
            *reinterpret_cast<uint4*>(sA + row * 136 + c8) = va;
            *reinterpret_cast<uint4*>(sB + row * 136 + c8) = vb;
        }
        __syncthreads();
#pragma unroll
        for (int ks = 0; ks < 8; ks++) {
            uint32_t a[4][4], b[2][4];
#pragma unroll
            for (int mt = 0; mt < 4; mt++) LDSM4(a[mt], a_base + (mt * 16 * 136 + ks * 16) * 2);
#pragma unroll
            for (int n2 = 0; n2 < 2; n2++) LDSM4(b[n2], b_base + (n2 * 16 * 136 + ks * 16) * 2);
#pragma unroll
            for (int mt = 0; mt < 4; mt++)
#pragma unroll
                for (int nt = 0; nt < 4; nt++)
                    MMA_BF16(acc[mt][nt], a[mt], b[nt >> 1][(nt & 1) * 2], b[nt >> 1][(nt & 1) * 2 + 1]);
        }
    }

    int r_base = r0 + wr * 64 + (lane >> 2);
    int c_base = c0 + wc * 32 + (lane & 3) * 2;
#pragma unroll
    for (int mt = 0; mt < 4; mt++) {
        int r_lo = r_base + mt * 16, r_hi = r_lo + 8;
#pragma unroll
        for (int nt = 0; nt < 4; nt++) {
            int c = c_base + nt * 8;
            if (c < Nn) {
                if (r_lo < Nn)
                    *reinterpret_cast<float2*>(&g_raw[r_lo * LD + c]) =
                        make_float2(acc[mt][nt][0], acc[mt][nt][1]);
                if (r_hi < Nn)
                    *reinterpret_cast<float2*>(&g_raw[r_hi * LD + c]) =
                        make_float2(acc[mt][nt][2], acc[mt][nt][3]);
            }
        }
    }
}

// ---------------- fused: x = w @ v (all heads) + asum = sum_h w -------------
// grid (8 m-windows, 32 r-blocks), 256 threads, dynamic smem
__global__ __launch_bounds__(256) void k_wx2(float* __restrict__ out) {
    extern __shared__ float smf[];
    float* invS1 = smf;                        // 64
    float* invS2 = smf + 64;                   // 64
    float* w_sm  = smf + 128;                  // [64][64]
    float* v_sm  = smf + 128 + 4096;           // [64][32]
    float* asum  = smf + 128 + 4096 + 2048;    // [64][256]
    int t = threadIdx.x;
    int r0 = blockIdx.y * 64;
    int mc = blockIdx.x * 256;
    int d = t & 31, rg = t >> 5;

    // zero asum (16384 floats)
#pragma unroll
    for (int i = 0; i < 16; i++)
        *reinterpret_cast<float4*>(&asum[t * 4 + i * 1024]) = make_float4(0.f, 0.f, 0.f, 0.f);

    for (int h = 0; h < Hh; h++) {
        const float* E1 = &g_e[0][h][0];
        const float* E2 = &g_e[1][h][0];
        __syncthreads();
        if (t < 64) {
            int r = r0 + t;
            invS1[t] = (r < Nn) ? 0.5f / g_S[0][h * Nn + r] : 0.f;
        } else if (t < 128) {
            int r = r0 + t - 64;
            invS2[t - 64] = (r < Nn) ? 0.5f / g_S[1][h * Nn + r] : 0.f;
        }
        float acc[8];
#pragma unroll
        for (int i = 0; i < 8; i++) acc[i] = 0.f;

        for (int mt = 0; mt < 4; mt++) {
            int m0 = mc + mt * 64;
            __syncthreads();
            // phase A: w tile + asum accumulation
#pragma unroll
            for (int i = 0; i < 4; i++) {
                int idx = t + i * 256;
                int rr = idx >> 4, m4 = (idx & 15) * 4;
                int r = r0 + rr, m = m0 + m4;
                float w[4] = {0.f, 0.f, 0.f, 0.f};
                if (r < Nn) {
                    int g = r * LD + m;
                    float4 a = *reinterpret_cast<const float4*>(&E1[g]);
                    float4 b = *reinterpret_cast<const float4*>(&E2[g]);
                    float is1 = invS1[rr], is2 = invS2[rr];
                    int bs = (r / 10) * 10;
                    float e1v[4] = {a.x, a.y, a.z, a.w};
                    float e2v[4] = {b.x, b.y, b.z, b.w};
#pragma unroll
                    for (int q = 0; q < 4; q++) {
                        int mm = m + q;
                        float wv = e1v[q] * is1 + e2v[q] * is2;
                        if (mm >= bs && mm < bs + 9 && mm != r) wv = 0.f;
                        w[q] = wv;
                    }
                    float4* ap = reinterpret_cast<float4*>(&asum[rr * 256 + mt * 64 + m4]);
                    float4 o = *ap;
                    o.x += w[0]; o.y += w[1]; o.z += w[2]; o.w += w[3];
                    *ap = o;
                }
                *reinterpret_cast<float4*>(&w_sm[rr * 64 + m4]) = make_float4(w[0], w[1], w[2], w[3]);
            }
            // v tile
#pragma unroll
            for (int i = 0; i < 2; i++) {
                int idx = t + i * 256;
                int mm = idx >> 3, d4 = (idx & 7) * 4;
                float4 vv = make_float4(0.f, 0.f, 0.f, 0.f);
                if (m0 + mm < Nn) vv = *reinterpret_cast<const float4*>(&g_v[(h * Nn + m0 + mm) * Dd + d4]);
                *reinterpret_cast<float4*>(&v_sm[mm * 32 + d4]) = vv;
            }
            __syncthreads();
            // phase B: x += w @ v
#pragma unroll 4
            for (int m4 = 0; m4 < 16; m4++) {
                float v0 = v_sm[(m4 * 4 + 0) * 32 + d];
                float v1 = v_sm[(m4 * 4 + 1) * 32 + d];
                float v2 = v_sm[(m4 * 4 + 2) * 32 + d];
                float v3 = v_sm[(m4 * 4 + 3) * 32 + d];
#pragma unroll
                for (int i = 0; i < 8; i++) {
                    float4 w4 = *reinterpret_cast<const float4*>(&w_sm[(rg * 8 + i) * 64 + m4 * 4]);
                    acc[i] = fmaf(w4.x, v0, acc[i]);
                    acc[i] = fmaf(w4.y, v1, acc[i]);
                    acc[i] = fmaf(w4.z, v2, acc[i]);
                    acc[i] = fmaf(w4.w, v3, acc[i]);
                }
            }
        }
#pragma unroll
        for (int i = 0; i < 8; i++) {
            int r = r0 + rg * 8 + i;
            if (r < Nn) atomicAdd(&out[r * 2 * Cc + h * Dd + d], acc[i]);
        }
    }
    __syncthreads();
    // write asum -> g_attn
#pragma unroll
    for (int i = 0; i < 16; i++) {
        int idx = t + i * 256;
        int rr = idx >> 6, mq = (idx & 63) * 4;
        int r = r0 + rr;
        if (r < Nn)
            *reinterpret_cast<float4*>(&g_attn[r * LD + mc + mq]) =
                *reinterpret_cast<const float4*>(&asum[rr * 256 + mq]);
    }
}

// ---------------- final sim: softmax of asum + masked renorm ----------------
__global__ __launch_bounds__(256) void k_sim2(float* __restrict__ out) {
    __shared__ float e_row[Nn];
    __shared__ float red[2][8];
    int r = blockIdx.x, t = threadIdx.x;
    float se = 0.f, sm = 0.f;
    for (int m4 = t * 4; m4 < Nn; m4 += 1024) {
        float4 a = *reinterpret_cast<const float4*>(&g_attn[r * LD + m4]);
        float4 rw = *reinterpret_cast<const float4*>(&g_raw[r * LD + m4]);
        float e0 = __expf(a.x * 0.125f), e1 = __expf(a.y * 0.125f);
        float e2 = __expf(a.z * 0.125f), e3 = __expf(a.w * 0.125f);
        e_row[m4 + 0] = e0; e_row[m4 + 1] = e1;
        e_row[m4 + 2] = e2; e_row[m4 + 3] = e3;
        se += e0 + e1 + e2 + e3;
        if (rw.x > 6.0f) sm += e0;
        if (rw.y > 6.0f) sm += e1;
        if (rw.z > 6.0f) sm += e2;
        if (rw.w > 6.0f) sm += e3;
    }
#pragma unroll
    for (int off = 16; off; off >>= 1) {
        se += __shfl_xor_sync(0xffffffffu, se, off);
        sm += __shfl_xor_sync(0xffffffffu, sm, off);
    }
    int wid = t >> 5, lane = t & 31;
    if (!lane) { red[0][wid] = se; red[1][wid] = sm; }
    __syncthreads();
    if (t == 0) {
        float a = 0.f, b = 0.f;
        for (int i = 0; i < 8; i++) { a += red[0][i]; b += red[1][i]; }
        red[0][0] = a; red[1][0] = b;
    }
    __syncthreads();
    float S = red[0][0], Sm = red[1][0];
    float invS = 1.f / S;
    float invden = 1.f / (Sm * invS + 1e-8f);
    float* orow = &out[Nn * 2 * Cc + r * Nn];
    for (int m4 = t * 4; m4 < Nn; m4 += 1024) {
        float4 rw = *reinterpret_cast<const float4*>(&g_raw[r * LD + m4]);
        float4 o;
        o.x = (rw.x > 6.0f) ? e_row[m4 + 0] * invS * invden : 0.f;
        o.y = (rw.y > 6.0f) ? e_row[m4 + 1] * invS * invden : 0.f;
        o.z = (rw.z > 6.0f) ? e_row[m4 + 2] * invS * invden : 0.f;
        o.w = (rw.w > 6.0f) ? e_row[m4 + 3] * invS * invden : 0.f;
        *reinterpret_cast<float4*>(&orow[m4]) = o;
    }
}

// ---------------- launch ----------------------------------------------------
extern "C" void kernel_launch(void* const* d_in, const int* in_sizes, int n_in,
                              void* d_out, int out_size) {
    const float* x_cls = (const float*)d_in[0];
    const float* x_reg = (const float*)d_in[1];
    const float* W_cls = (const float*)d_in[2];
    const float* W_reg = (const float*)d_in[3];
    float* out = (float*)d_out;

    const int SM_T = 2 * 128 * 136 * 2;                 // 69632 B
    const int SM_W = (128 + 4096 + 2048 + 16384) * 4;   // 90624 B
    cudaFuncSetAttribute(k_logits_t, cudaFuncAttributeMaxDynamicSharedMemorySize, SM_T);
    cudaFuncSetAttribute(k_raw_t, cudaFuncAttributeMaxDynamicSharedMemorySize, SM_T);
    cudaFuncSetAttribute(k_wx2, cudaFuncAttributeMaxDynamicSharedMemorySize, SM_W);

    k_zeroS<<<(2 * Hh * Nn + 255) / 256, 256>>>();
    k_gemm<<<dim3(6, 16, 2), 256>>>(x_cls, W_cls, x_reg, W_reg);
    k_norm<<<Nn, 256>>>(out);
    k_logits_t<<<dim3(16, 16, 16), 256, SM_T>>>();
    k_raw_t<<<dim3(16, 16), 256, SM_T>>>();
    k_wx2<<<dim3(8, 32), 256, SM_W>>>(out);
    k_sim2<<<Nn, 256>>>(out);
}

// round 8
// speedup vs baseline: 1.1964x; 1.1964x over previous
#include <cuda_runtime.h>
#include <cuda_bf16.h>
#include <math.h>
#include <stdint.h>

#define Nn 2000
#define Cc 256
#define Hh 8
#define Dd 32
#define LD 2048
#define N3C 768

// ---------------- scratch (static __device__, no allocation) ----------------
__device__ float g_qkv[2][Nn * N3C];             // raw qkv for cls/reg
__device__ float g_v[Hh * Nn * Dd];              // raw v_cls [h][n][d]
__device__ __nv_bfloat16 g_qA[2][Hh * Nn * 128]; // q split, A-side dup [hi,lo,hi,lo]
__device__ __nv_bfloat16 g_kB[2][Hh * Nn * 128]; // k split, B-side dup [hi,hi,lo,lo]
__device__ __nv_bfloat16 g_vnP[Nn * 256];        // vn plain bf16, head-concat [n][h*32+d]
__device__ __nv_bfloat16 g_e[2][Hh][Nn * LD];    // exp(logits) per (p, head), bf16
__device__ float g_raw[Nn * LD];                 // sum over heads of vn@vn^T
__device__ float g_S[2][Hh * Nn];                // softmax row sums (fp32, of rounded e)

// ---------------- PTX helpers ----------------
__device__ __forceinline__ uint32_t smem_u32(const void* p) {
    uint32_t r;
    asm("{ .reg .u64 t; cvta.to.shared.u64 t, %1; cvt.u32.u64 %0, t; }" : "=r"(r) : "l"(p));
    return r;
}
#define LDSM4(r, addr) \
    asm volatile("ldmatrix.sync.aligned.m8n8.x4.shared.b16 {%0,%1,%2,%3}, [%4];" \
        : "=r"((r)[0]), "=r"((r)[1]), "=r"((r)[2]), "=r"((r)[3]) : "r"(addr))
#define MMA_BF16(c, a, b0v, b1v) \
    asm volatile("mma.sync.aligned.m16n8k16.row.col.f32.bf16.bf16.f32 " \
        "{%0,%1,%2,%3}, {%4,%5,%6,%7}, {%8,%9}, {%0,%1,%2,%3};" \
        : "+f"((c)[0]), "+f"((c)[1]), "+f"((c)[2]), "+f"((c)[3]) \
        : "r"((a)[0]), "r"((a)[1]), "r"((a)[2]), "r"((a)[3]), "r"(b0v), "r"(b1v))

// ---------------- zero row sums ----------------
__global__ void k_zeroS() {
    int i = blockIdx.x * 256 + threadIdx.x;
    if (i < 2 * Hh * Nn) ((float*)g_S)[i] = 0.f;
}

// ---------------- QKV GEMM: [2000,256] @ [256,768] --------------------------
__global__ __launch_bounds__(256) void k_gemm(const float* __restrict__ xc,
                                              const float* __restrict__ wc,
                                              const float* __restrict__ xr,
                                              const float* __restrict__ wr) {
    __shared__ float sa[32][132];
    __shared__ float sb[32][132];
    int z = blockIdx.z;
    const float* A = z ? xr : xc;
    const float* B = z ? wr : wc;
    float* Cout = g_qkv[z];
    int t = threadIdx.x, ty = t >> 4, tx = t & 15;
    int r0 = blockIdx.y * 128, c0 = blockIdx.x * 128;
    float acc[8][8];
#pragma unroll
    for (int i = 0; i < 8; i++)
#pragma unroll
        for (int j = 0; j < 8; j++) acc[i][j] = 0.f;

    for (int kk0 = 0; kk0 < Cc; kk0 += 32) {
        __syncthreads();
#pragma unroll
        for (int i = 0; i < 4; i++) {
            int idx = t + i * 256;
            int rr = idx >> 3, d4 = (idx & 7) * 4;
            float4 av = make_float4(0.f, 0.f, 0.f, 0.f);
            if (r0 + rr < Nn) av = *reinterpret_cast<const float4*>(&A[(r0 + rr) * Cc + kk0 + d4]);
            sa[d4 + 0][rr] = av.x; sa[d4 + 1][rr] = av.y;
            sa[d4 + 2][rr] = av.z; sa[d4 + 3][rr] = av.w;
        }
#pragma unroll
        for (int i = 0; i < 4; i++) {
            int idx = t + i * 256;
            int rr = idx >> 5, c4 = (idx & 31) * 4;
            float4 bv = *reinterpret_cast<const float4*>(&B[(kk0 + rr) * N3C + c0 + c4]);
            *reinterpret_cast<float4*>(&sb[rr][c4]) = bv;
        }
        __syncthreads();
#pragma unroll
        for (int kk = 0; kk < 32; kk++) {
            float4 a0 = *reinterpret_cast<const float4*>(&sa[kk][ty * 8]);
            float4 a1 = *reinterpret_cast<const float4*>(&sa[kk][ty * 8 + 4]);
            float4 b0 = *reinterpret_cast<const float4*>(&sb[kk][tx * 8]);
            float4 b1 = *reinterpret_cast<const float4*>(&sb[kk][tx * 8 + 4]);
            float a[8] = {a0.x, a0.y, a0.z, a0.w, a1.x, a1.y, a1.z, a1.w};
            float b[8] = {b0.x, b0.y, b0.z, b0.w, b1.x, b1.y, b1.z, b1.w};
#pragma unroll
            for (int i = 0; i < 8; i++)
#pragma unroll
                for (int j = 0; j < 8; j++) acc[i][j] = fmaf(a[i], b[j], acc[i][j]);
        }
    }
#pragma unroll
    for (int i = 0; i < 8; i++) {
        int gr = r0 + ty * 8 + i;
        if (gr < Nn) {
            float* dst = &Cout[gr * N3C + c0 + tx * 8];
            *reinterpret_cast<float4*>(dst) = make_float4(acc[i][0], acc[i][1], acc[i][2], acc[i][3]);
            *reinterpret_cast<float4*>(dst + 4) = make_float4(acc[i][4], acc[i][5], acc[i][6], acc[i][7]);
        }
    }
}

// ---------------- normalize + bf16-split + emit x_ori ----------------------
__device__ __forceinline__ float rnorm_of(float x) {
    float s = x * x;
#pragma unroll
    for (int off = 16; off; off >>= 1) s += __shfl_xor_sync(0xffffffffu, s, off);
    return 1.f / (sqrtf(s) + 1e-8f);
}
__device__ __forceinline__ void split_A(__nv_bfloat16* p, int d, float x) {
    __nv_bfloat16 hi = __float2bfloat16(x);
    __nv_bfloat16 lo = __float2bfloat16(x - __bfloat162float(hi));
    p[d] = hi; p[32 + d] = lo; p[64 + d] = hi; p[96 + d] = lo;
}
__device__ __forceinline__ void split_B(__nv_bfloat16* p, int d, float x) {
    __nv_bfloat16 hi = __float2bfloat16(x);
    __nv_bfloat16 lo = __float2bfloat16(x - __bfloat162float(hi));
    p[d] = hi; p[32 + d] = hi; p[64 + d] = lo; p[96 + d] = lo;
}

__global__ __launch_bounds__(256) void k_norm(float* __restrict__ out) {
    int n = blockIdx.x;
    int h = threadIdx.x >> 5;
    int d = threadIdx.x & 31;
    const float* rc = g_qkv[0] + n * N3C;
    const float* rr = g_qkv[1] + n * N3C;
    float qc = rc[h * Dd + d], kc = rc[Cc + h * Dd + d], vc = rc[2 * Cc + h * Dd + d];
    float qr = rr[h * Dd + d], kr = rr[Cc + h * Dd + d];

    float qcn = qc * rnorm_of(qc), kcn = kc * rnorm_of(kc), vcn = vc * rnorm_of(vc);
    float qrn = qr * rnorm_of(qr), krn = kr * rnorm_of(kr);

    int base = (h * Nn + n) * 128;
    split_A(&g_qA[0][base], d, qcn);
    split_A(&g_qA[1][base], d, qrn);
    split_B(&g_kB[0][base], d, kcn);
    split_B(&g_kB[1][base], d, krn);
    g_vnP[n * 256 + h * Dd + d] = __float2bfloat16(vcn);
    g_v[(h * Nn + n) * Dd + d] = vc;

    out[n * 2 * Cc + h * Dd + d] = 0.f;
    out[n * 2 * Cc + Cc + h * Dd + d] = vc;
}

// ---------------- tensor logits: all heads+p in one launch ------------------
__global__ __launch_bounds__(256) void k_logits_t() {
    extern __shared__ __nv_bfloat16 smbf[];
    __nv_bfloat16* sA = smbf;                 // [128][136]
    __nv_bfloat16* sB = smbf + 128 * 136;
    int t = threadIdx.x, lane = t & 31, wid = t >> 5;
    int wr = wid >> 2, wc = wid & 3;
    int c0 = blockIdx.x * 128, r0 = blockIdx.y * 128;
    int p = blockIdx.z & 1, h = blockIdx.z >> 1;
    const __nv_bfloat16* A = g_qA[p] + h * Nn * 128;
    const __nv_bfloat16* B = g_kB[p] + h * Nn * 128;

#pragma unroll
    for (int i = 0; i < 8; i++) {
        int idx = t + i * 256;
        int row = idx >> 4, c8 = (idx & 15) * 8;
        uint4 va = make_uint4(0, 0, 0, 0), vb = make_uint4(0, 0, 0, 0);
        if (r0 + row < Nn) va = *reinterpret_cast<const uint4*>(A + (r0 + row) * 128 + c8);
        if (c0 + row < Nn) vb = *reinterpret_cast<const uint4*>(B + (c0 + row) * 128 + c8);
        *reinterpret_cast<uint4*>(sA + row * 136 + c8) = va;
        *reinterpret_cast<uint4*>(sB + row * 136 + c8) = vb;
    }
    __syncthreads();

    uint32_t a_base = smem_u32(sA) + ((wr * 64 + (lane & 15)) * 136 + (lane >> 4) * 8) * 2;
    int bn = (lane & 7) + (lane >> 4) * 8;
    uint32_t b_base = smem_u32(sB) + ((wc * 32 + bn) * 136 + ((lane >> 3) & 1) * 8) * 2;

    float acc[4][4][4];
#pragma unroll
    for (int i = 0; i < 4; i++)
#pragma unroll
        for (int j = 0; j < 4; j++)
#pragma unroll
            for (int q = 0; q < 4; q++) acc[i][j][q] = 0.f;

#pragma unroll
    for (int ks = 0; ks < 8; ks++) {
        uint32_t a[4][4], b[2][4];
#pragma unroll
        for (int mt = 0; mt < 4; mt++) LDSM4(a[mt], a_base + (mt * 16 * 136 + ks * 16) * 2);
#pragma unroll
        for (int n2 = 0; n2 < 2; n2++) LDSM4(b[n2], b_base + (n2 * 16 * 136 + ks * 16) * 2);
#pragma unroll
        for (int mt = 0; mt < 4; mt++)
#pragma unroll
            for (int nt = 0; nt < 4; nt++)
                MMA_BF16(acc[mt][nt], a[mt], b[nt >> 1][(nt & 1) * 2], b[nt >> 1][(nt & 1) * 2 + 1]);
    }

    __nv_bfloat16* E = &g_e[p][h][0];
    float* S = &g_S[p][h * Nn];
    int r_base = r0 + wr * 64 + (lane >> 2);
    int c_base = c0 + wc * 32 + (lane & 3) * 2;
#pragma unroll
    for (int mt = 0; mt < 4; mt++) {
        int r_lo = r_base + mt * 16, r_hi = r_lo + 8;
        float rs_lo = 0.f, rs_hi = 0.f;
#pragma unroll
        for (int nt = 0; nt < 4; nt++) {
            int c = c_base + nt * 8;
            bool cok = (c < Nn);
            float e0 = cok ? __expf(25.f * acc[mt][nt][0] - 25.f) : 0.f;
            float e1 = cok ? __expf(25.f * acc[mt][nt][1] - 25.f) : 0.f;
            float e2 = cok ? __expf(25.f * acc[mt][nt][2] - 25.f) : 0.f;
            float e3 = cok ? __expf(25.f * acc[mt][nt][3] - 25.f) : 0.f;
            // round to bf16 FIRST; S sums the rounded values (self-consistent softmax)
            __nv_bfloat162 blo = __floats2bfloat162_rn(e0, e1);
            __nv_bfloat162 bhi = __floats2bfloat162_rn(e2, e3);
            float2 flo = __bfloat1622float2(blo), fhi = __bfloat1622float2(bhi);
            rs_lo += flo.x + flo.y;
            rs_hi += fhi.x + fhi.y;
            if (cok && r_lo < Nn) *reinterpret_cast<__nv_bfloat162*>(&E[r_lo * LD + c]) = blo;
            if (cok && r_hi < Nn) *reinterpret_cast<__nv_bfloat162*>(&E[r_hi * LD + c]) = bhi;
        }
        rs_lo += __shfl_xor_sync(0xffffffffu, rs_lo, 1);
        rs_lo += __shfl_xor_sync(0xffffffffu, rs_lo, 2);
        rs_hi += __shfl_xor_sync(0xffffffffu, rs_hi, 1);
        rs_hi += __shfl_xor_sync(0xffffffffu, rs_hi, 2);
        if ((lane & 3) == 0) {
            if (r_lo < Nn) atomicAdd(&S[r_lo], rs_lo);
            if (r_hi < Nn) atomicAdd(&S[r_hi], rs_hi);
        }
    }
}

// ---------------- tensor raw: sum over heads of vn@vn^T (K=256 bf16) --------
__global__ __launch_bounds__(256) void k_raw_t() {
    extern __shared__ __nv_bfloat16 smbf[];
    __nv_bfloat16* sA = smbf;
    __nv_bfloat16* sB = smbf + 128 * 136;
    int t = threadIdx.x, lane = t & 31, wid = t >> 5;
    int wr = wid >> 2, wc = wid & 3;
    int c0 = blockIdx.x * 128, r0 = blockIdx.y * 128;

    float acc[4][4][4];
#pragma unroll
    for (int i = 0; i < 4; i++)
#pragma unroll
        for (int j = 0; j < 4; j++)
#pragma unroll
            for (int q = 0; q < 4; q++) acc[i][j][q] = 0.f;

    uint32_t a_base = smem_u32(sA) + ((wr * 64 + (lane & 15)) * 136 + (lane >> 4) * 8) * 2;
    int bn = (lane & 7) + (lane >> 4) * 8;
    uint32_t b_base = smem_u32(sB) + ((wc * 32 + bn) * 136 + ((lane >> 3) & 1) * 8) * 2;

    for (int kc = 0; kc < 2; kc++) {
        __syncthreads();
#pragma unroll
        for (int i = 0; i < 8; i++) {
            int idx = t + i * 256;
            int row = idx >> 4, c8 = (idx & 15) * 8;
            uint4 va = make_uint4(0, 0, 0, 0), vb = make_uint4(0, 0, 0, 0);
            if (r0 + row < Nn) va = *reinterpret_cast<const uint4*>(&g_vnP[(r0 + row) * 256 + kc * 128 + c8]);
            if (c0 + row < Nn) vb = *reinterpret_cast<const uint4*>(&g_vnP[(c0 + row) * 256 + kc * 128 + c8]);
            *reinterpret_cast<uint4*>(sA + row * 136 + c8) = va;
            *reinterpret_cast<uint4*>(sB + row * 136 + c8) = vb;
        }
        __syncthreads();
#pragma unroll
        for (int ks = 0; ks < 8; ks++) {
            uint32_t a[4][4], b[2][4];
#pragma unroll
            for (int mt = 0; mt < 4; mt++) LDSM4(a[mt], a_base + (mt * 16 * 136 + ks * 16) * 2);
#pragma unroll
            for (int n2 = 0; n2 < 2; n2++) LDSM4(b[n2], b_base + (n2 * 16 * 136 + ks * 16) * 2);
#pragma unroll
            for (int mt = 0; mt < 4; mt++)
#pragma unroll
                for (int nt = 0; nt < 4; nt++)
                    MMA_BF16(acc[mt][nt], a[mt], b[nt >> 1][(nt & 1) * 2], b[nt >> 1][(nt & 1) * 2 + 1]);
        }
    }

    int r_base = r0 + wr * 64 + (lane >> 2);
    int c_base = c0 + wc * 32 + (lane & 3) * 2;
#pragma unroll
    for (int mt = 0; mt < 4; mt++) {
        int r_lo = r_base + mt * 16, r_hi = r_lo + 8;
#pragma unroll
        for (int nt = 0; nt < 4; nt++) {
            int c = c_base + nt * 8;
            if (c < Nn) {
                if (r_lo < Nn)
                    *reinterpret_cast<float2*>(&g_raw[r_lo * LD + c]) =
                        make_float2(acc[mt][nt][0], acc[mt][nt][1]);
                if (r_hi < Nn)
                    *reinterpret_cast<float2*>(&g_raw[r_hi * LD + c]) =
                        make_float2(acc[mt][nt][2], acc[mt][nt][3]);
            }
        }
    }
}

// ---------------- per-head x = w @ v (z = 8 heads) ---------------------------
__global__ __launch_bounds__(256) void k_wx(float* __restrict__ out) {
    __shared__ float invS1[64], invS2[64];
    __shared__ float w_sm[64][64];
    __shared__ float v_sm[64][32];
    int h = blockIdx.z;
    int t = threadIdx.x;
    int r0 = blockIdx.y * 64;
    int mc = blockIdx.x * 256;
    const __nv_bfloat16* E1 = &g_e[0][h][0];
    const __nv_bfloat16* E2 = &g_e[1][h][0];

    if (t < 64) {
        int r = r0 + t;
        invS1[t] = (r < Nn) ? 0.5f / g_S[0][h * Nn + r] : 0.f;
    } else if (t < 128) {
        int r = r0 + t - 64;
        invS2[t - 64] = (r < Nn) ? 0.5f / g_S[1][h * Nn + r] : 0.f;
    }
    int d = t & 31, rg = t >> 5;
    float acc[8];
#pragma unroll
    for (int i = 0; i < 8; i++) acc[i] = 0.f;

    for (int mt = 0; mt < 4; mt++) {
        int m0 = mc + mt * 64;
        __syncthreads();
#pragma unroll
        for (int i = 0; i < 4; i++) {
            int idx = t + i * 256;
            int rr = idx >> 4, m4 = (idx & 15) * 4;
            int r = r0 + rr, m = m0 + m4;
            float w[4] = {0.f, 0.f, 0.f, 0.f};
            if (r < Nn) {
                int g = r * LD + m;
                const __nv_bfloat162* pa = reinterpret_cast<const __nv_bfloat162*>(&E1[g]);
                const __nv_bfloat162* pb = reinterpret_cast<const __nv_bfloat162*>(&E2[g]);
                float2 a0 = __bfloat1622float2(pa[0]), a1 = __bfloat1622float2(pa[1]);
                float2 b0 = __bfloat1622float2(pb[0]), b1 = __bfloat1622float2(pb[1]);
                float e1v[4] = {a0.x, a0.y, a1.x, a1.y};
                float e2v[4] = {b0.x, b0.y, b1.x, b1.y};
                float is1 = invS1[rr], is2 = invS2[rr];
                int bs = (r / 10) * 10;
#pragma unroll
                for (int q = 0; q < 4; q++) {
                    int mm = m + q;
                    float wv = e1v[q] * is1 + e2v[q] * is2;
                    if (mm >= bs && mm < bs + 9 && mm != r) wv = 0.f;
                    w[q] = wv;
                }
            }
            *reinterpret_cast<float4*>(&w_sm[rr][m4]) = make_float4(w[0], w[1], w[2], w[3]);
        }
#pragma unroll
        for (int i = 0; i < 2; i++) {
            int idx = t + i * 256;
            int mm = idx >> 3, d4 = (idx & 7) * 4;
            float4 vv = make_float4(0.f, 0.f, 0.f, 0.f);
            if (m0 + mm < Nn) vv = *reinterpret_cast<const float4*>(&g_v[(h * Nn + m0 + mm) * Dd + d4]);
            *reinterpret_cast<float4*>(&v_sm[mm][d4]) = vv;
        }
        __syncthreads();
#pragma unroll 4
        for (int m4 = 0; m4 < 16; m4++) {
            float v0 = v_sm[m4 * 4 + 0][d];
            float v1 = v_sm[m4 * 4 + 1][d];
            float v2 = v_sm[m4 * 4 + 2][d];
            float v3 = v_sm[m4 * 4 + 3][d];
#pragma unroll
            for (int i = 0; i < 8; i++) {
                float4 w4 = *reinterpret_cast<const float4*>(&w_sm[rg * 8 + i][m4 * 4]);
                acc[i] = fmaf(w4.x, v0, acc[i]);
                acc[i] = fmaf(w4.y, v1, acc[i]);
                acc[i] = fmaf(w4.z, v2, acc[i]);
                acc[i] = fmaf(w4.w, v3, acc[i]);
            }
        }
    }
#pragma unroll
    for (int i = 0; i < 8; i++) {
        int r = r0 + rg * 8 + i;
        if (r < Nn) atomicAdd(&out[r * 2 * Cc + h * Dd + d], acc[i]);
    }
}

// ---------------- final sim: recompute sum_h w, softmax, mask, renorm -------
__global__ __launch_bounds__(256) void k_sim(float* __restrict__ out) {
    __shared__ float e_row[Nn];
    __shared__ float red[2][8];
    __shared__ float sinv[16];
    int r = blockIdx.x, t = threadIdx.x;
    if (t < 16) {
        int p = t >> 3, hh = t & 7;
        sinv[t] = 0.5f / g_S[p][hh * Nn + r];
    }
    __syncthreads();
    int bs = (r / 10) * 10;
    float se = 0.f, sm = 0.f;
    for (int m4 = t * 4; m4 < Nn; m4 += 1024) {
        float ac[4] = {0.f, 0.f, 0.f, 0.f};
#pragma unroll
        for (int p = 0; p < 2; p++)
#pragma unroll
            for (int hh = 0; hh < 8; hh++) {
                const __nv_bfloat162* pe = reinterpret_cast<const __nv_bfloat162*>(&g_e[p][hh][r * LD + m4]);
                float2 f0 = __bfloat1622float2(pe[0]), f1 = __bfloat1622float2(pe[1]);
                float is = sinv[p * 8 + hh];
                ac[0] = fmaf(f0.x, is, ac[0]);
                ac[1] = fmaf(f0.y, is, ac[1]);
                ac[2] = fmaf(f1.x, is, ac[2]);
                ac[3] = fmaf(f1.y, is, ac[3]);
            }
#pragma unroll
        for (int q = 0; q < 4; q++) {
            int mm = m4 + q;
            if (mm >= bs && mm < bs + 9 && mm != r) ac[q] = 0.f;
        }
        float4 rw = *reinterpret_cast<const float4*>(&g_raw[r * LD + m4]);
        float e0 = __expf(ac[0] * 0.125f), e1 = __expf(ac[1] * 0.125f);
        float e2 = __expf(ac[2] * 0.125f), e3 = __expf(ac[3] * 0.125f);
        e_row[m4 + 0] = e0; e_row[m4 + 1] = e1;
        e_row[m4 + 2] = e2; e_row[m4 + 3] = e3;
        se += e0 + e1 + e2 + e3;
        if (rw.x > 6.0f) sm += e0;
        if (rw.y > 6.0f) sm += e1;
        if (rw.z > 6.0f) sm += e2;
        if (rw.w > 6.0f) sm += e3;
    }
#pragma unroll
    for (int off = 16; off; off >>= 1) {
        se += __shfl_xor_sync(0xffffffffu, se, off);
        sm += __shfl_xor_sync(0xffffffffu, sm, off);
    }
    int wid = t >> 5, lane = t & 31;
    if (!lane) { red[0][wid] = se; red[1][wid] = sm; }
    __syncthreads();
    if (t == 0) {
        float a = 0.f, b = 0.f;
        for (int i = 0; i < 8; i++) { a += red[0][i]; b += red[1][i]; }
        red[0][0] = a; red[1][0] = b;
    }
    __syncthreads();
    float S = red[0][0], Sm = red[1][0];
    float invS = 1.f / S;
    float invden = 1.f / (Sm * invS + 1e-8f);
    float* orow = &out[Nn * 2 * Cc + r * Nn];
    for (int m4 = t * 4; m4 < Nn; m4 += 1024) {
        float4 rw = *reinterpret_cast<const float4*>(&g_raw[r * LD + m4]);
        float4 o;
        o.x = (rw.x > 6.0f) ? e_row[m4 + 0] * invS * invden : 0.f;
        o.y = (rw.y > 6.0f) ? e_row[m4 + 1] * invS * invden : 0.f;
        o.z = (rw.z > 6.0f) ? e_row[m4 + 2] * invS * invden : 0.f;
        o.w = (rw.w > 6.0f) ? e_row[m4 + 3] * invS * invden : 0.f;
        *reinterpret_cast<float4*>(&orow[m4]) = o;
    }
}

// ---------------- launch ----------------------------------------------------
extern "C" void kernel_launch(void* const* d_in, const int* in_sizes, int n_in,
                              void* d_out, int out_size) {
    const float* x_cls = (const float*)d_in[0];
    const float* x_reg = (const float*)d_in[1];
    const float* W_cls = (const float*)d_in[2];
    const float* W_reg = (const float*)d_in[3];
    float* out = (float*)d_out;

    const int SM_T = 2 * 128 * 136 * 2;   // 69632 B
    cudaFuncSetAttribute(k_logits_t, cudaFuncAttributeMaxDynamicSharedMemorySize, SM_T);
    cudaFuncSetAttribute(k_raw_t, cudaFuncAttributeMaxDynamicSharedMemorySize, SM_T);

    k_zeroS<<<(2 * Hh * Nn + 255) / 256, 256>>>();
    k_gemm<<<dim3(6, 16, 2), 256>>>(x_cls, W_cls, x_reg, W_reg);
    k_norm<<<Nn, 256>>>(out);
    k_logits_t<<<dim3(16, 16, 16), 256, SM_T>>>();
    k_raw_t<<<dim3(16, 16), 256, SM_T>>>();
    k_wx<<<dim3(8, 32, 8), 256>>>(out);
    k_sim<<<Nn, 256>>>(out);
}

// round 13
// speedup vs baseline: 1.4277x; 1.1933x over previous
#include <cuda_runtime.h>
#include <cuda_bf16.h>
#include <math.h>
#include <stdint.h>

#define Nn 2000
#define Cc 256
#define Hh 8
#define Dd 32
#define LD 2048
#define N3C 768

// ---------------- scratch (static __device__, no allocation) ----------------
__device__ float g_qkv[2][Nn * N3C];             // raw qkv for cls/reg
__device__ float g_v[Hh * Nn * Dd];              // raw v_cls [h][n][d]
__device__ __nv_bfloat16 g_qA[2][Hh * Nn * 128]; // q split, A-side dup [hi,lo,hi,lo]
__device__ __nv_bfloat16 g_kB[2][Hh * Nn * 128]; // k split, B-side dup [hi,hi,lo,lo]
__device__ __nv_bfloat16 g_vnP[Nn * 256];        // vn plain bf16, head-concat [n][h*32+d]
__device__ __nv_bfloat16 g_e[2][Hh][2048 * LD];  // exp(logits), bf16, ROW-PADDED to 2048
__device__ __nv_bfloat16 g_vThi[Hh * 32 * LD];   // v^T hi [h*32+d][n]
__device__ __nv_bfloat16 g_vTlo[Hh * 32 * LD];   // v^T lo
__device__ float g_raw[Nn * LD];                 // sum over heads of vn@vn^T
__device__ float g_S[2][Hh * Nn];                // softmax row sums (fp32, of rounded e)

// ---------------- PTX helpers ----------------
__device__ __forceinline__ uint32_t smem_u32(const void* p) {
    uint32_t r;
    asm("{ .reg .u64 t; cvta.to.shared.u64 t, %1; cvt.u32.u64 %0, t; }" : "=r"(r) : "l"(p));
    return r;
}
#define LDSM4(r, addr) \
    asm volatile("ldmatrix.sync.aligned.m8n8.x4.shared.b16 {%0,%1,%2,%3}, [%4];" \
        : "=r"((r)[0]), "=r"((r)[1]), "=r"((r)[2]), "=r"((r)[3]) : "r"(addr))
#define MMA_BF16(c, a, b0v, b1v) \
    asm volatile("mma.sync.aligned.m16n8k16.row.col.f32.bf16.bf16.f32 " \
        "{%0,%1,%2,%3}, {%4,%5,%6,%7}, {%8,%9}, {%0,%1,%2,%3};" \
        : "+f"((c)[0]), "+f"((c)[1]), "+f"((c)[2]), "+f"((c)[3]) \
        : "r"((a)[0]), "r"((a)[1]), "r"((a)[2]), "r"((a)[3]), "r"(b0v), "r"(b1v))

// ---------------- zero row sums ----------------
__global__ void k_zeroS() {
    int i = blockIdx.x * 256 + threadIdx.x;
    if (i < 2 * Hh * Nn) ((float*)g_S)[i] = 0.f;
}

// ---------------- QKV GEMM: [2000,256] @ [256,768] --------------------------
__global__ __launch_bounds__(256) void k_gemm(const float* __restrict__ xc,
                                              const float* __restrict__ wc,
                                              const float* __restrict__ xr,
                                              const float* __restrict__ wr) {
    __shared__ float sa[32][132];
    __shared__ float sb[32][132];
    int z = blockIdx.z;
    const float* A = z ? xr : xc;
    const float* B = z ? wr : wc;
    float* Cout = g_qkv[z];
    int t = threadIdx.x, ty = t >> 4, tx = t & 15;
    int r0 = blockIdx.y * 128, c0 = blockIdx.x * 128;
    float acc[8][8];
#pragma unroll
    for (int i = 0; i < 8; i++)
#pragma unroll
        for (int j = 0; j < 8; j++) acc[i][j] = 0.f;

    for (int kk0 = 0; kk0 < Cc; kk0 += 32) {
        __syncthreads();
#pragma unroll
        for (int i = 0; i < 4; i++) {
            int idx = t + i * 256;
            int rr = idx >> 3, d4 = (idx & 7) * 4;
            float4 av = make_float4(0.f, 0.f, 0.f, 0.f);
            if (r0 + rr < Nn) av = *reinterpret_cast<const float4*>(&A[(r0 + rr) * Cc + kk0 + d4]);
            sa[d4 + 0][rr] = av.x; sa[d4 + 1][rr] = av.y;
            sa[d4 + 2][rr] = av.z; sa[d4 + 3][rr] = av.w;
        }
#pragma unroll
        for (int i = 0; i < 4; i++) {
            int idx = t + i * 256;
            int rr = idx >> 5, c4 = (idx & 31) * 4;
            float4 bv = *reinterpret_cast<const float4*>(&B[(kk0 + rr) * N3C + c0 + c4]);
            *reinterpret_cast<float4*>(&sb[rr][c4]) = bv;
        }
        __syncthreads();
#pragma unroll
        for (int kk = 0; kk < 32; kk++) {
            float4 a0 = *reinterpret_cast<const float4*>(&sa[kk][ty * 8]);
            float4 a1 = *reinterpret_cast<const float4*>(&sa[kk][ty * 8 + 4]);
            float4 b0 = *reinterpret_cast<const float4*>(&sb[kk][tx * 8]);
            float4 b1 = *reinterpret_cast<const float4*>(&sb[kk][tx * 8 + 4]);
            float a[8] = {a0.x, a0.y, a0.z, a0.w, a1.x, a1.y, a1.z, a1.w};
            float b[8] = {b0.x, b0.y, b0.z, b0.w, b1.x, b1.y, b1.z, b1.w};
#pragma unroll
            for (int i = 0; i < 8; i++)
#pragma unroll
                for (int j = 0; j < 8; j++) acc[i][j] = fmaf(a[i], b[j], acc[i][j]);
        }
    }
#pragma unroll
    for (int i = 0; i < 8; i++) {
        int gr = r0 + ty * 8 + i;
        if (gr < Nn) {
            float* dst = &Cout[gr * N3C + c0 + tx * 8];
            *reinterpret_cast<float4*>(dst) = make_float4(acc[i][0], acc[i][1], acc[i][2], acc[i][3]);
            *reinterpret_cast<float4*>(dst + 4) = make_float4(acc[i][4], acc[i][5], acc[i][6], acc[i][7]);
        }
    }
}

// ---------------- normalize + bf16-split + emit x_ori ----------------------
__device__ __forceinline__ float rnorm_of(float x) {
    float s = x * x;
#pragma unroll
    for (int off = 16; off; off >>= 1) s += __shfl_xor_sync(0xffffffffu, s, off);
    return 1.f / (sqrtf(s) + 1e-8f);
}
__device__ __forceinline__ void split_A(__nv_bfloat16* p, int d, float x) {
    __nv_bfloat16 hi = __float2bfloat16(x);
    __nv_bfloat16 lo = __float2bfloat16(x - __bfloat162float(hi));
    p[d] = hi; p[32 + d] = lo; p[64 + d] = hi; p[96 + d] = lo;
}
__device__ __forceinline__ void split_B(__nv_bfloat16* p, int d, float x) {
    __nv_bfloat16 hi = __float2bfloat16(x);
    __nv_bfloat16 lo = __float2bfloat16(x - __bfloat162float(hi));
    p[d] = hi; p[32 + d] = hi; p[64 + d] = lo; p[96 + d] = lo;
}

__global__ __launch_bounds__(256) void k_norm(float* __restrict__ out) {
    int n = blockIdx.x;
    int h = threadIdx.x >> 5;
    int d = threadIdx.x & 31;
    const float* rc = g_qkv[0] + n * N3C;
    const float* rr = g_qkv[1] + n * N3C;
    float qc = rc[h * Dd + d], kc = rc[Cc + h * Dd + d], vc = rc[2 * Cc + h * Dd + d];
    float qr = rr[h * Dd + d], kr = rr[Cc + h * Dd + d];

    float qcn = qc * rnorm_of(qc), kcn = kc * rnorm_of(kc), vcn = vc * rnorm_of(vc);
    float qrn = qr * rnorm_of(qr), krn = kr * rnorm_of(kr);

    int base = (h * Nn + n) * 128;
    split_A(&g_qA[0][base], d, qcn);
    split_A(&g_qA[1][base], d, qrn);
    split_B(&g_kB[0][base], d, kcn);
    split_B(&g_kB[1][base], d, krn);
    g_vnP[n * 256 + h * Dd + d] = __float2bfloat16(vcn);
    g_v[(h * Nn + n) * Dd + d] = vc;

    out[n * 2 * Cc + h * Dd + d] = 0.f;
    out[n * 2 * Cc + Cc + h * Dd + d] = vc;
}

// ---------------- transpose v -> vT hi/lo bf16 ------------------------------
// grid (32 ntiles, 8 h), 256 threads
__global__ __launch_bounds__(256) void k_vt() {
    __shared__ float sv[64][33];
    int h = blockIdx.y, n0 = blockIdx.x * 64;
    int t = threadIdx.x;
    // load 64 n-rows x 32 d (coalesced)
#pragma unroll
    for (int i = 0; i < 2; i++) {
        int idx = t + i * 256;
        int nr = idx >> 3, d4 = (idx & 7) * 4;
        float4 vv = make_float4(0.f, 0.f, 0.f, 0.f);
        if (n0 + nr < Nn) vv = *reinterpret_cast<const float4*>(&g_v[(h * Nn + n0 + nr) * Dd + d4]);
        sv[nr][d4] = vv.x; sv[nr][d4 + 1] = vv.y; sv[nr][d4 + 2] = vv.z; sv[nr][d4 + 3] = vv.w;
    }
    __syncthreads();
    // write vT rows: d = t>>3, n-offset (t&7)*8; 8 bf16 per thread (coalesced)
    int d = t >> 3, nc = (t & 7) * 8;
    __nv_bfloat16 hibuf[8], lobuf[8];
#pragma unroll
    for (int q = 0; q < 8; q++) {
        float x = sv[nc + q][d];
        __nv_bfloat16 hi = __float2bfloat16(x);
        hibuf[q] = hi;
        lobuf[q] = __float2bfloat16(x - __bfloat162float(hi));
    }
    int o = (h * 32 + d) * LD + n0 + nc;
    *reinterpret_cast<uint4*>(&g_vThi[o]) = *reinterpret_cast<const uint4*>(hibuf);
    *reinterpret_cast<uint4*>(&g_vTlo[o]) = *reinterpret_cast<const uint4*>(lobuf);
}

// ---------------- tensor logits: all heads+p in one launch ------------------
__global__ __launch_bounds__(256) void k_logits_t() {
    extern __shared__ __nv_bfloat16 smbf[];
    __nv_bfloat16* sA = smbf;                 // [128][136]
    __nv_bfloat16* sB = smbf + 128 * 136;
    int t = threadIdx.x, lane = t & 31, wid = t >> 5;
    int wr = wid >> 2, wc = wid & 3;
    int c0 = blockIdx.x * 128, r0 = blockIdx.y * 128;
    int p = blockIdx.z & 1, h = blockIdx.z >> 1;
    const __nv_bfloat16* A = g_qA[p] + h * Nn * 128;
    const __nv_bfloat16* B = g_kB[p] + h * Nn * 128;

#pragma unroll
    for (int i = 0; i < 8; i++) {
        int idx = t + i * 256;
        int row = idx >> 4, c8 = (idx & 15) * 8;
        uint4 va = make_uint4(0, 0, 0, 0), vb = make_uint4(0, 0, 0, 0);
        if (r0 + row < Nn) va = *reinterpret_cast<const uint4*>(A + (r0 + row) * 128 + c8);
        if (c0 + row < Nn) vb = *reinterpret_cast<const uint4*>(B + (c0 + row) * 128 + c8);
        *reinterpret_cast<uint4*>(sA + row * 136 + c8) = va;
        *reinterpret_cast<uint4*>(sB + row * 136 + c8) = vb;
    }
    __syncthreads();

    uint32_t a_base = smem_u32(sA) + ((wr * 64 + (lane & 15)) * 136 + (lane >> 4) * 8) * 2;
    int bn = (lane & 7) + (lane >> 4) * 8;
    uint32_t b_base = smem_u32(sB) + ((wc * 32 + bn) * 136 + ((lane >> 3) & 1) * 8) * 2;

    float acc[4][4][4];
#pragma unroll
    for (int i = 0; i < 4; i++)
#pragma unroll
        for (int j = 0; j < 4; j++)
#pragma unroll
            for (int q = 0; q < 4; q++) acc[i][j][q] = 0.f;

#pragma unroll
    for (int ks = 0; ks < 8; ks++) {
        uint32_t a[4][4], b[2][4];
#pragma unroll
        for (int mt = 0; mt < 4; mt++) LDSM4(a[mt], a_base + (mt * 16 * 136 + ks * 16) * 2);
#pragma unroll
        for (int n2 = 0; n2 < 2; n2++) LDSM4(b[n2], b_base + (n2 * 16 * 136 + ks * 16) * 2);
#pragma unroll
        for (int mt = 0; mt < 4; mt++)
#pragma unroll
            for (int nt = 0; nt < 4; nt++)
                MMA_BF16(acc[mt][nt], a[mt], b[nt >> 1][(nt & 1) * 2], b[nt >> 1][(nt & 1) * 2 + 1]);
    }

    __nv_bfloat16* E = &g_e[p][h][0];
    float* S = &g_S[p][h * Nn];
    int r_base = r0 + wr * 64 + (lane >> 2);
    int c_base = c0 + wc * 32 + (lane & 3) * 2;
#pragma unroll
    for (int mt = 0; mt < 4; mt++) {
        int r_lo = r_base + mt * 16, r_hi = r_lo + 8;
        float rs_lo = 0.f, rs_hi = 0.f;
#pragma unroll
        for (int nt = 0; nt < 4; nt++) {
            int c = c_base + nt * 8;
            bool cok = (c < Nn);
            float e0 = cok ? __expf(25.f * acc[mt][nt][0] - 25.f) : 0.f;
            float e1 = cok ? __expf(25.f * acc[mt][nt][1] - 25.f) : 0.f;
            float e2 = cok ? __expf(25.f * acc[mt][nt][2] - 25.f) : 0.f;
            float e3 = cok ? __expf(25.f * acc[mt][nt][3] - 25.f) : 0.f;
            __nv_bfloat162 blo = __floats2bfloat162_rn(e0, e1);
            __nv_bfloat162 bhi = __floats2bfloat162_rn(e2, e3);
            float2 flo = __bfloat1622float2(blo), fhi = __bfloat1622float2(bhi);
            rs_lo += flo.x + flo.y;
            rs_hi += fhi.x + fhi.y;
            if (cok && r_lo < Nn) *reinterpret_cast<__nv_bfloat162*>(&E[r_lo * LD + c]) = blo;
            if (cok && r_hi < Nn) *reinterpret_cast<__nv_bfloat162*>(&E[r_hi * LD + c]) = bhi;
        }
        rs_lo += __shfl_xor_sync(0xffffffffu, rs_lo, 1);
        rs_lo += __shfl_xor_sync(0xffffffffu, rs_lo, 2);
        rs_hi += __shfl_xor_sync(0xffffffffu, rs_hi, 1);
        rs_hi += __shfl_xor_sync(0xffffffffu, rs_hi, 2);
        if ((lane & 3) == 0) {
            if (r_lo < Nn) atomicAdd(&S[r_lo], rs_lo);
            if (r_hi < Nn) atomicAdd(&S[r_hi], rs_hi);
        }
    }
}

// ---------------- tensor raw: sum over heads of vn@vn^T (K=256 bf16) --------
__global__ __launch_bounds__(256) void k_raw_t() {
    extern __shared__ __nv_bfloat16 smbf[];
    __nv_bfloat16* sA = smbf;
    __nv_bfloat16* sB = smbf + 128 * 136;
    int t = threadIdx.x, lane = t & 31, wid = t >> 5;
    int wr = wid >> 2, wc = wid & 3;
    int c0 = blockIdx.x * 128, r0 = blockIdx.y * 128;

    float acc[4][4][4];
#pragma unroll
    for (int i = 0; i < 4; i++)
#pragma unroll
        for (int j = 0; j < 4; j++)
#pragma unroll
            for (int q = 0; q < 4; q++) acc[i][j][q] = 0.f;

    uint32_t a_base = smem_u32(sA) + ((wr * 64 + (lane & 15)) * 136 + (lane >> 4) * 8) * 2;
    int bn = (lane & 7) + (lane >> 4) * 8;
    uint32_t b_base = smem_u32(sB) + ((wc * 32 + bn) * 136 + ((lane >> 3) & 1) * 8) * 2;

    for (int kc = 0; kc < 2; kc++) {
        __syncthreads();
#pragma unroll
        for (int i = 0; i < 8; i++) {
            int idx = t + i * 256;
            int row = idx >> 4, c8 = (idx & 15) * 8;
            uint4 va = make_uint4(0, 0, 0, 0), vb = make_uint4(0, 0, 0, 0);
            if (r0 + row < Nn) va = *reinterpret_cast<const uint4*>(&g_vnP[(r0 + row) * 256 + kc * 128 + c8]);
            if (c0 + row < Nn) vb = *reinterpret_cast<const uint4*>(&g_vnP[(c0 + row) * 256 + kc * 128 + c8]);
            *reinterpret_cast<uint4*>(sA + row * 136 + c8) = va;
            *reinterpret_cast<uint4*>(sB + row * 136 + c8) = vb;
        }
        __syncthreads();
#pragma unroll
        for (int ks = 0; ks < 8; ks++) {
            uint32_t a[4][4], b[2][4];
#pragma unroll
            for (int mt = 0; mt < 4; mt++) LDSM4(a[mt], a_base + (mt * 16 * 136 + ks * 16) * 2);
#pragma unroll
            for (int n2 = 0; n2 < 2; n2++) LDSM4(b[n2], b_base + (n2 * 16 * 136 + ks * 16) * 2);
#pragma unroll
            for (int mt = 0; mt < 4; mt++)
#pragma unroll
                for (int nt = 0; nt < 4; nt++)
                    MMA_BF16(acc[mt][nt], a[mt], b[nt >> 1][(nt & 1) * 2], b[nt >> 1][(nt & 1) * 2 + 1]);
        }
    }

    int r_base = r0 + wr * 64 + (lane >> 2);
    int c_base = c0 + wc * 32 + (lane & 3) * 2;
#pragma unroll
    for (int mt = 0; mt < 4; mt++) {
        int r_lo = r_base + mt * 16, r_hi = r_lo + 8;
#pragma unroll
        for (int nt = 0; nt < 4; nt++) {
            int c = c_base + nt * 8;
            if (c < Nn) {
                if (r_lo < Nn)
                    *reinterpret_cast<float2*>(&g_raw[r_lo * LD + c]) =
                        make_float2(acc[mt][nt][0], acc[mt][nt][1]);
                if (r_hi < Nn)
                    *reinterpret_cast<float2*>(&g_raw[r_hi * LD + c]) =
                        make_float2(acc[mt][nt][2], acc[mt][nt][3]);
            }
        }
    }
}

// ---------------- tensor w@v: x = is1*(E1@V) + is2*(E2@V), unmasked ---------
// grid (2 m-halves, 32 r-tiles(64), 8 heads), 256 threads (8 warps = 4m x 2n)
__global__ __launch_bounds__(256) void k_wx_t(float* __restrict__ out) {
    extern __shared__ __nv_bfloat16 smw[];
    __nv_bfloat16* sE1 = smw;                       // [64][136]
    __nv_bfloat16* sE2 = smw + 64 * 136;            // [64][136]
    __nv_bfloat16* sVh = smw + 2 * 64 * 136;        // [32][136]
    __nv_bfloat16* sVl = sVh + 32 * 136;            // [32][136]
    int t = threadIdx.x, lane = t & 31, wid = t >> 5;
    int wr = wid >> 1, wc = wid & 1;
    int mh = blockIdx.x, r0 = blockIdx.y * 64, h = blockIdx.z;
    const __nv_bfloat16* E1 = &g_e[0][h][0];
    const __nv_bfloat16* E2 = &g_e[1][h][0];
    const __nv_bfloat16* Vh = &g_vThi[h * 32 * LD];
    const __nv_bfloat16* Vl = &g_vTlo[h * 32 * LD];

    uint32_t a1_base = smem_u32(sE1) + ((wr * 16 + (lane & 15)) * 136 + (lane >> 4) * 8) * 2;
    uint32_t a2_base = smem_u32(sE2) + ((wr * 16 + (lane & 15)) * 136 + (lane >> 4) * 8) * 2;
    int bn = (lane & 7) + (lane >> 4) * 8;
    uint32_t bh_base = smem_u32(sVh) + ((wc * 16 + bn) * 136 + ((lane >> 3) & 1) * 8) * 2;
    uint32_t bl_base = smem_u32(sVl) + ((wc * 16 + bn) * 136 + ((lane >> 3) & 1) * 8) * 2;

    float c1[2][4], c2[2][4];
#pragma unroll
    for (int nt = 0; nt < 2; nt++)
#pragma unroll
        for (int q = 0; q < 4; q++) { c1[nt][q] = 0.f; c2[nt][q] = 0.f; }

    for (int ch = 0; ch < 8; ch++) {
        int m0 = mh * 1024 + ch * 128;
        __syncthreads();
        // E tiles: 64 rows x 128 cols (rows padded in gmem; no guards needed)
#pragma unroll
        for (int i = 0; i < 4; i++) {
            int idx = t + i * 256;
            int row = idx >> 4, c8 = (idx & 15) * 8;
            *reinterpret_cast<uint4*>(sE1 + row * 136 + c8) =
                *reinterpret_cast<const uint4*>(E1 + (r0 + row) * LD + m0 + c8);
            *reinterpret_cast<uint4*>(sE2 + row * 136 + c8) =
                *reinterpret_cast<const uint4*>(E2 + (r0 + row) * LD + m0 + c8);
        }
        // vT tiles: 32 rows x 128 cols
#pragma unroll
        for (int i = 0; i < 2; i++) {
            int idx = t + i * 256;
            int row = idx >> 4, c8 = (idx & 15) * 8;
            *reinterpret_cast<uint4*>(sVh + row * 136 + c8) =
                *reinterpret_cast<const uint4*>(Vh + row * LD + m0 + c8);
            *reinterpret_cast<uint4*>(sVl + row * 136 + c8) =
                *reinterpret_cast<const uint4*>(Vl + row * LD + m0 + c8);
        }
        __syncthreads();
#pragma unroll
        for (int ks = 0; ks < 8; ks++) {
            uint32_t a1[4], a2[4], bh[4], bl[4];
            LDSM4(a1, a1_base + ks * 32);
            LDSM4(a2, a2_base + ks * 32);
            LDSM4(bh, bh_base + ks * 32);
            LDSM4(bl, bl_base + ks * 32);
#pragma unroll
            for (int nt = 0; nt < 2; nt++) {
                MMA_BF16(c1[nt], a1, bh[nt * 2], bh[nt * 2 + 1]);
                MMA_BF16(c1[nt], a1, bl[nt * 2], bl[nt * 2 + 1]);
                MMA_BF16(c2[nt], a2, bh[nt * 2], bh[nt * 2 + 1]);
                MMA_BF16(c2[nt], a2, bl[nt * 2], bl[nt * 2 + 1]);
            }
        }
    }

    int r_lo = r0 + wr * 16 + (lane >> 2);
    int r_hi = r_lo + 8;
    float is1_lo = 0.f, is2_lo = 0.f, is1_hi = 0.f, is2_hi = 0.f;
    if (r_lo < Nn) { is1_lo = 0.5f / g_S[0][h * Nn + r_lo]; is2_lo = 0.5f / g_S[1][h * Nn + r_lo]; }
    if (r_hi < Nn) { is1_hi = 0.5f / g_S[0][h * Nn + r_hi]; is2_hi = 0.5f / g_S[1][h * Nn + r_hi]; }
#pragma unroll
    for (int nt = 0; nt < 2; nt++) {
        int d = wc * 16 + nt * 8 + (lane & 3) * 2;
        if (r_lo < Nn) {
            atomicAdd(&out[r_lo * 2 * Cc + h * Dd + d],     c1[nt][0] * is1_lo + c2[nt][0] * is2_lo);
            atomicAdd(&out[r_lo * 2 * Cc + h * Dd + d + 1], c1[nt][1] * is1_lo + c2[nt][1] * is2_lo);
        }
        if (r_hi < Nn) {
            atomicAdd(&out[r_hi * 2 * Cc + h * Dd + d],     c1[nt][2] * is1_hi + c2[nt][2] * is2_hi);
            atomicAdd(&out[r_hi * 2 * Cc + h * Dd + d + 1], c1[nt][3] * is1_hi + c2[nt][3] * is2_hi);
        }
    }
}

// ---------------- exact mask correction: subtract zeroed block terms --------
// grid 2000 blocks, 256 threads (h = t>>5, d = t&31)
__global__ __launch_bounds__(256) void k_fix(float* __restrict__ out) {
    int r = blockIdx.x, t = threadIdx.x;
    int h = t >> 5, d = t & 31;
    int bs = (r / 10) * 10;
    float is1 = 0.5f / g_S[0][h * Nn + r];
    float is2 = 0.5f / g_S[1][h * Nn + r];
    float acc = 0.f;
#pragma unroll
    for (int j = 0; j < 9; j++) {
        int m = bs + j;
        if (m == r) continue;
        float e1 = __bfloat162float(g_e[0][h][r * LD + m]);
        float e2 = __bfloat162float(g_e[1][h][r * LD + m]);
        float w = e1 * is1 + e2 * is2;
        acc = fmaf(w, g_v[(h * Nn + m) * Dd + d], acc);
    }
    int o = r * 2 * Cc + h * Dd + d;
    out[o] -= acc;
}

// ---------------- final sim: recompute sum_h w, softmax, mask, renorm -------
__global__ __launch_bounds__(256) void k_sim(float* __restrict__ out) {
    __shared__ float e_row[Nn];
    __shared__ float red[2][8];
    __shared__ float sinv[16];
    int r = blockIdx.x, t = threadIdx.x;
    if (t < 16) {
        int p = t >> 3, hh = t & 7;
        sinv[t] = 0.5f / g_S[p][hh * Nn + r];
    }
    __syncthreads();
    int bs = (r / 10) * 10;
    float se = 0.f, sm = 0.f;
    for (int m4 = t * 4; m4 < Nn; m4 += 1024) {
        float ac[4] = {0.f, 0.f, 0.f, 0.f};
#pragma unroll
        for (int p = 0; p < 2; p++)
#pragma unroll
            for (int hh = 0; hh < 8; hh++) {
                const __nv_bfloat162* pe = reinterpret_cast<const __nv_bfloat162*>(&g_e[p][hh][r * LD + m4]);
                float2 f0 = __bfloat1622float2(pe[0]), f1 = __bfloat1622float2(pe[1]);
                float is = sinv[p * 8 + hh];
                ac[0] = fmaf(f0.x, is, ac[0]);
                ac[1] = fmaf(f0.y, is, ac[1]);
                ac[2] = fmaf(f1.x, is, ac[2]);
                ac[3] = fmaf(f1.y, is, ac[3]);
            }
#pragma unroll
        for (int q = 0; q < 4; q++) {
            int mm = m4 + q;
            if (mm >= bs && mm < bs + 9 && mm != r) ac[q] = 0.f;
        }
        float4 rw = *reinterpret_cast<const float4*>(&g_raw[r * LD + m4]);
        float e0 = __expf(ac[0] * 0.125f), e1 = __expf(ac[1] * 0.125f);
        float e2 = __expf(ac[2] * 0.125f), e3 = __expf(ac[3] * 0.125f);
        e_row[m4 + 0] = e0; e_row[m4 + 1] = e1;
        e_row[m4 + 2] = e2; e_row[m4 + 3] = e3;
        se += e0 + e1 + e2 + e3;
        if (rw.x > 6.0f) sm += e0;
        if (rw.y > 6.0f) sm += e1;
        if (rw.z > 6.0f) sm += e2;
        if (rw.w > 6.0f) sm += e3;
    }
#pragma unroll
    for (int off = 16; off; off >>= 1) {
        se += __shfl_xor_sync(0xffffffffu, se, off);
        sm += __shfl_xor_sync(0xffffffffu, sm, off);
    }
    int wid = t >> 5, lane = t & 31;
    if (!lane) { red[0][wid] = se; red[1][wid] = sm; }
    __syncthreads();
    if (t == 0) {
        float a = 0.f, b = 0.f;
        for (int i = 0; i < 8; i++) { a += red[0][i]; b += red[1][i]; }
        red[0][0] = a; red[1][0] = b;
    }
    __syncthreads();
    float S = red[0][0], Sm = red[1][0];
    float invS = 1.f / S;
    float invden = 1.f / (Sm * invS + 1e-8f);
    float* orow = &out[Nn * 2 * Cc + r * Nn];
    for (int m4 = t * 4; m4 < Nn; m4 += 1024) {
        float4 rw = *reinterpret_cast<const float4*>(&g_raw[r * LD + m4]);
        float4 o;
        o.x = (rw.x > 6.0f) ? e_row[m4 + 0] * invS * invden : 0.f;
        o.y = (rw.y > 6.0f) ? e_row[m4 + 1] * invS * invden : 0.f;
        o.z = (rw.z > 6.0f) ? e_row[m4 + 2] * invS * invden : 0.f;
        o.w = (rw.w > 6.0f) ? e_row[m4 + 3] * invS * invden : 0.f;
        *reinterpret_cast<float4*>(&orow[m4]) = o;
    }
}

// ---------------- launch ----------------------------------------------------
extern "C" void kernel_launch(void* const* d_in, const int* in_sizes, int n_in,
                              void* d_out, int out_size) {
    const float* x_cls = (const float*)d_in[0];
    const float* x_reg = (const float*)d_in[1];
    const float* W_cls = (const float*)d_in[2];
    const float* W_reg = (const float*)d_in[3];
    float* out = (float*)d_out;

    const int SM_T = 2 * 128 * 136 * 2;            // 69632 B
    const int SM_W = (2 * 64 + 2 * 32) * 136 * 2;  // 52224 B
    cudaFuncSetAttribute(k_logits_t, cudaFuncAttributeMaxDynamicSharedMemorySize, SM_T);
    cudaFuncSetAttribute(k_raw_t, cudaFuncAttributeMaxDynamicSharedMemorySize, SM_T);
    cudaFuncSetAttribute(k_wx_t, cudaFuncAttributeMaxDynamicSharedMemorySize, SM_W);

    k_zeroS<<<(2 * Hh * Nn + 255) / 256, 256>>>();
    k_gemm<<<dim3(6, 16, 2), 256>>>(x_cls, W_cls, x_reg, W_reg);
    k_norm<<<Nn, 256>>>(out);
    k_vt<<<dim3(32, 8), 256>>>();
    k_logits_t<<<dim3(16, 16, 16), 256, SM_T>>>();
    k_raw_t<<<dim3(16, 16), 256, SM_T>>>();
    k_wx_t<<<dim3(2, 32, 8), 256, SM_W>>>(out);
    k_fix<<<Nn, 256>>>(out);
    k_sim<<<Nn, 256>>>(out);
}

// round 14
// speedup vs baseline: 1.4803x; 1.0368x over previous
#include <cuda_runtime.h>
#include <cuda_bf16.h>
#include <math.h>
#include <stdint.h>

#define Nn 2000
#define Cc 256
#define Hh 8
#define Dd 32
#define LD 2048
#define N3C 768

// ---------------- scratch (static __device__, no allocation) ----------------
__device__ float g_qkv[2][Nn * N3C];             // raw qkv for cls/reg
__device__ float g_v[Hh * Nn * Dd];              // raw v_cls [h][n][d]
__device__ __nv_bfloat16 g_qA[2][Hh * Nn * 128]; // q split, A-side [hi,lo,hi,-]
__device__ __nv_bfloat16 g_kB[2][Hh * Nn * 128]; // k split, B-side [hi,hi,lo,-]
__device__ __nv_bfloat16 g_vnP[Nn * 256];        // vn plain bf16, head-concat [n][h*32+d]
__device__ __nv_bfloat16 g_e[2][Hh][2048 * LD];  // exp(logits), bf16, ROW-PADDED to 2048
__device__ __nv_bfloat16 g_vThi[Hh * 32 * LD];   // v^T hi [h*32+d][n]  (cols >= Nn are 0)
__device__ __nv_bfloat16 g_vTlo[Hh * 32 * LD];   // v^T lo
__device__ float g_attn[Nn * LD];                // sum over heads of masked w
__device__ float g_raw[Nn * LD];                 // sum over heads of vn@vn^T
__device__ float g_S[2][Hh * Nn];                // softmax row sums (fp32, of rounded e)

// ---------------- PTX helpers ----------------
__device__ __forceinline__ uint32_t smem_u32(const void* p) {
    uint32_t r;
    asm("{ .reg .u64 t; cvta.to.shared.u64 t, %1; cvt.u32.u64 %0, t; }" : "=r"(r) : "l"(p));
    return r;
}
#define LDSM4(r, addr) \
    asm volatile("ldmatrix.sync.aligned.m8n8.x4.shared.b16 {%0,%1,%2,%3}, [%4];" \
        : "=r"((r)[0]), "=r"((r)[1]), "=r"((r)[2]), "=r"((r)[3]) : "r"(addr))
#define MMA_BF16(c, a, b0v, b1v) \
    asm volatile("mma.sync.aligned.m16n8k16.row.col.f32.bf16.bf16.f32 " \
        "{%0,%1,%2,%3}, {%4,%5,%6,%7}, {%8,%9}, {%0,%1,%2,%3};" \
        : "+f"((c)[0]), "+f"((c)[1]), "+f"((c)[2]), "+f"((c)[3]) \
        : "r"((a)[0]), "r"((a)[1]), "r"((a)[2]), "r"((a)[3]), "r"(b0v), "r"(b1v))

// ---------------- zero row sums ----------------
__global__ void k_zeroS() {
    int i = blockIdx.x * 256 + threadIdx.x;
    if (i < 2 * Hh * Nn) ((float*)g_S)[i] = 0.f;
}

// ---------------- QKV GEMM: [2000,256] @ [256,768] --------------------------
__global__ __launch_bounds__(256) void k_gemm(const float* __restrict__ xc,
                                              const float* __restrict__ wc,
                                              const float* __restrict__ xr,
                                              const float* __restrict__ wr) {
    __shared__ float sa[32][132];
    __shared__ float sb[32][132];
    int z = blockIdx.z;
    const float* A = z ? xr : xc;
    const float* B = z ? wr : wc;
    float* Cout = g_qkv[z];
    int t = threadIdx.x, ty = t >> 4, tx = t & 15;
    int r0 = blockIdx.y * 128, c0 = blockIdx.x * 128;
    float acc[8][8];
#pragma unroll
    for (int i = 0; i < 8; i++)
#pragma unroll
        for (int j = 0; j < 8; j++) acc[i][j] = 0.f;

    for (int kk0 = 0; kk0 < Cc; kk0 += 32) {
        __syncthreads();
#pragma unroll
        for (int i = 0; i < 4; i++) {
            int idx = t + i * 256;
            int rr = idx >> 3, d4 = (idx & 7) * 4;
            float4 av = make_float4(0.f, 0.f, 0.f, 0.f);
            if (r0 + rr < Nn) av = *reinterpret_cast<const float4*>(&A[(r0 + rr) * Cc + kk0 + d4]);
            sa[d4 + 0][rr] = av.x; sa[d4 + 1][rr] = av.y;
            sa[d4 + 2][rr] = av.z; sa[d4 + 3][rr] = av.w;
        }
#pragma unroll
        for (int i = 0; i < 4; i++) {
            int idx = t + i * 256;
            int rr = idx >> 5, c4 = (idx & 31) * 4;
            float4 bv = *reinterpret_cast<const float4*>(&B[(kk0 + rr) * N3C + c0 + c4]);
            *reinterpret_cast<float4*>(&sb[rr][c4]) = bv;
        }
        __syncthreads();
#pragma unroll
        for (int kk = 0; kk < 32; kk++) {
            float4 a0 = *reinterpret_cast<const float4*>(&sa[kk][ty * 8]);
            float4 a1 = *reinterpret_cast<const float4*>(&sa[kk][ty * 8 + 4]);
            float4 b0 = *reinterpret_cast<const float4*>(&sb[kk][tx * 8]);
            float4 b1 = *reinterpret_cast<const float4*>(&sb[kk][tx * 8 + 4]);
            float a[8] = {a0.x, a0.y, a0.z, a0.w, a1.x, a1.y, a1.z, a1.w};
            float b[8] = {b0.x, b0.y, b0.z, b0.w, b1.x, b1.y, b1.z, b1.w};
#pragma unroll
            for (int i = 0; i < 8; i++)
#pragma unroll
                for (int j = 0; j < 8; j++) acc[i][j] = fmaf(a[i], b[j], acc[i][j]);
        }
    }
#pragma unroll
    for (int i = 0; i < 8; i++) {
        int gr = r0 + ty * 8 + i;
        if (gr < Nn) {
            float* dst = &Cout[gr * N3C + c0 + tx * 8];
            *reinterpret_cast<float4*>(dst) = make_float4(acc[i][0], acc[i][1], acc[i][2], acc[i][3]);
            *reinterpret_cast<float4*>(dst + 4) = make_float4(acc[i][4], acc[i][5], acc[i][6], acc[i][7]);
        }
    }
}

// ---------------- normalize + bf16-split (K=96 pattern) + emit x_ori -------
__device__ __forceinline__ float rnorm_of(float x) {
    float s = x * x;
#pragma unroll
    for (int off = 16; off; off >>= 1) s += __shfl_xor_sync(0xffffffffu, s, off);
    return 1.f / (sqrtf(s) + 1e-8f);
}
// A-side: [hi, lo, hi]  B-side: [hi, hi, lo]  -> hi*hi + lo*hi + hi*lo
__device__ __forceinline__ void split_A(__nv_bfloat16* p, int d, float x) {
    __nv_bfloat16 hi = __float2bfloat16(x);
    __nv_bfloat16 lo = __float2bfloat16(x - __bfloat162float(hi));
    p[d] = hi; p[32 + d] = lo; p[64 + d] = hi;
}
__device__ __forceinline__ void split_B(__nv_bfloat16* p, int d, float x) {
    __nv_bfloat16 hi = __float2bfloat16(x);
    __nv_bfloat16 lo = __float2bfloat16(x - __bfloat162float(hi));
    p[d] = hi; p[32 + d] = hi; p[64 + d] = lo;
}

__global__ __launch_bounds__(256) void k_norm(float* __restrict__ out) {
    int n = blockIdx.x;
    int h = threadIdx.x >> 5;
    int d = threadIdx.x & 31;
    const float* rc = g_qkv[0] + n * N3C;
    const float* rr = g_qkv[1] + n * N3C;
    float qc = rc[h * Dd + d], kc = rc[Cc + h * Dd + d], vc = rc[2 * Cc + h * Dd + d];
    float qr = rr[h * Dd + d], kr = rr[Cc + h * Dd + d];

    float qcn = qc * rnorm_of(qc), kcn = kc * rnorm_of(kc), vcn = vc * rnorm_of(vc);
    float qrn = qr * rnorm_of(qr), krn = kr * rnorm_of(kr);

    int base = (h * Nn + n) * 128;
    split_A(&g_qA[0][base], d, qcn);
    split_A(&g_qA[1][base], d, qrn);
    split_B(&g_kB[0][base], d, kcn);
    split_B(&g_kB[1][base], d, krn);
    g_vnP[n * 256 + h * Dd + d] = __float2bfloat16(vcn);
    g_v[(h * Nn + n) * Dd + d] = vc;

    out[n * 2 * Cc + h * Dd + d] = 0.f;
    out[n * 2 * Cc + Cc + h * Dd + d] = vc;
}

// ---------------- transpose v -> vT hi/lo bf16 ------------------------------
__global__ __launch_bounds__(256) void k_vt() {
    __shared__ float sv[64][33];
    int h = blockIdx.y, n0 = blockIdx.x * 64;
    int t = threadIdx.x;
#pragma unroll
    for (int i = 0; i < 2; i++) {
        int idx = t + i * 256;
        int nr = idx >> 3, d4 = (idx & 7) * 4;
        float4 vv = make_float4(0.f, 0.f, 0.f, 0.f);
        if (n0 + nr < Nn) vv = *reinterpret_cast<const float4*>(&g_v[(h * Nn + n0 + nr) * Dd + d4]);
        sv[nr][d4] = vv.x; sv[nr][d4 + 1] = vv.y; sv[nr][d4 + 2] = vv.z; sv[nr][d4 + 3] = vv.w;
    }
    __syncthreads();
    int d = t >> 3, nc = (t & 7) * 8;
    __nv_bfloat16 hibuf[8], lobuf[8];
#pragma unroll
    for (int q = 0; q < 8; q++) {
        float x = sv[nc + q][d];
        __nv_bfloat16 hi = __float2bfloat16(x);
        hibuf[q] = hi;
        lobuf[q] = __float2bfloat16(x - __bfloat162float(hi));
    }
    int o = (h * 32 + d) * LD + n0 + nc;
    *reinterpret_cast<uint4*>(&g_vThi[o]) = *reinterpret_cast<const uint4*>(hibuf);
    *reinterpret_cast<uint4*>(&g_vTlo[o]) = *reinterpret_cast<const uint4*>(lobuf);
}

// ---------------- tensor logits: all heads+p, K=96 --------------------------
__global__ __launch_bounds__(256) void k_logits_t() {
    extern __shared__ __nv_bfloat16 smbf[];
    __nv_bfloat16* sA = smbf;                 // [128][136] (only 96 cols used)
    __nv_bfloat16* sB = smbf + 128 * 136;
    int t = threadIdx.x, lane = t & 31, wid = t >> 5;
    int wr = wid >> 2, wc = wid & 3;
    int c0 = blockIdx.x * 128, r0 = blockIdx.y * 128;
    int p = blockIdx.z & 1, h = blockIdx.z >> 1;
    const __nv_bfloat16* A = g_qA[p] + h * Nn * 128;
    const __nv_bfloat16* B = g_kB[p] + h * Nn * 128;

    // load 128 rows x 96 cols each
#pragma unroll
    for (int i = 0; i < 6; i++) {
        int idx = t + i * 256;          // 0..1535
        int row = idx / 12, c8 = (idx % 12) * 8;
        uint4 va = make_uint4(0, 0, 0, 0), vb = make_uint4(0, 0, 0, 0);
        if (r0 + row < Nn) va = *reinterpret_cast<const uint4*>(A + (r0 + row) * 128 + c8);
        if (c0 + row < Nn) vb = *reinterpret_cast<const uint4*>(B + (c0 + row) * 128 + c8);
        *reinterpret_cast<uint4*>(sA + row * 136 + c8) = va;
        *reinterpret_cast<uint4*>(sB + row * 136 + c8) = vb;
    }
    __syncthreads();

    uint32_t a_base = smem_u32(sA) + ((wr * 64 + (lane & 15)) * 136 + (lane >> 4) * 8) * 2;
    int bn = (lane & 7) + (lane >> 4) * 8;
    uint32_t b_base = smem_u32(sB) + ((wc * 32 + bn) * 136 + ((lane >> 3) & 1) * 8) * 2;

    float acc[4][4][4];
#pragma unroll
    for (int i = 0; i < 4; i++)
#pragma unroll
        for (int j = 0; j < 4; j++)
#pragma unroll
            for (int q = 0; q < 4; q++) acc[i][j][q] = 0.f;

#pragma unroll
    for (int ks = 0; ks < 6; ks++) {
        uint32_t a[4][4], b[2][4];
#pragma unroll
        for (int mt = 0; mt < 4; mt++) LDSM4(a[mt], a_base + (mt * 16 * 136 + ks * 16) * 2);
#pragma unroll
        for (int n2 = 0; n2 < 2; n2++) LDSM4(b[n2], b_base + (n2 * 16 * 136 + ks * 16) * 2);
#pragma unroll
        for (int mt = 0; mt < 4; mt++)
#pragma unroll
            for (int nt = 0; nt < 4; nt++)
                MMA_BF16(acc[mt][nt], a[mt], b[nt >> 1][(nt & 1) * 2], b[nt >> 1][(nt & 1) * 2 + 1]);
    }

    __nv_bfloat16* E = &g_e[p][h][0];
    float* S = &g_S[p][h * Nn];
    int r_base = r0 + wr * 64 + (lane >> 2);
    int c_base = c0 + wc * 32 + (lane & 3) * 2;
#pragma unroll
    for (int mt = 0; mt < 4; mt++) {
        int r_lo = r_base + mt * 16, r_hi = r_lo + 8;
        float rs_lo = 0.f, rs_hi = 0.f;
#pragma unroll
        for (int nt = 0; nt < 4; nt++) {
            int c = c_base + nt * 8;
            bool cok = (c < Nn);
            float e0 = cok ? __expf(25.f * acc[mt][nt][0] - 25.f) : 0.f;
            float e1 = cok ? __expf(25.f * acc[mt][nt][1] - 25.f) : 0.f;
            float e2 = cok ? __expf(25.f * acc[mt][nt][2] - 25.f) : 0.f;
            float e3 = cok ? __expf(25.f * acc[mt][nt][3] - 25.f) : 0.f;
            __nv_bfloat162 blo = __floats2bfloat162_rn(e0, e1);
            __nv_bfloat162 bhi = __floats2bfloat162_rn(e2, e3);
            float2 flo = __bfloat1622float2(blo), fhi = __bfloat1622float2(bhi);
            rs_lo += flo.x + flo.y;
            rs_hi += fhi.x + fhi.y;
            if (cok && r_lo < Nn) *reinterpret_cast<__nv_bfloat162*>(&E[r_lo * LD + c]) = blo;
            if (cok && r_hi < Nn) *reinterpret_cast<__nv_bfloat162*>(&E[r_hi * LD + c]) = bhi;
        }
        rs_lo += __shfl_xor_sync(0xffffffffu, rs_lo, 1);
        rs_lo += __shfl_xor_sync(0xffffffffu, rs_lo, 2);
        rs_hi += __shfl_xor_sync(0xffffffffu, rs_hi, 1);
        rs_hi += __shfl_xor_sync(0xffffffffu, rs_hi, 2);
        if ((lane & 3) == 0) {
            if (r_lo < Nn) atomicAdd(&S[r_lo], rs_lo);
            if (r_hi < Nn) atomicAdd(&S[r_hi], rs_hi);
        }
    }
}

// ---------------- tensor raw: sum over heads of vn@vn^T (K=256 bf16) --------
__global__ __launch_bounds__(256) void k_raw_t() {
    extern __shared__ __nv_bfloat16 smbf[];
    __nv_bfloat16* sA = smbf;
    __nv_bfloat16* sB = smbf + 128 * 136;
    int t = threadIdx.x, lane = t & 31, wid = t >> 5;
    int wr = wid >> 2, wc = wid & 3;
    int c0 = blockIdx.x * 128, r0 = blockIdx.y * 128;

    float acc[4][4][4];
#pragma unroll
    for (int i = 0; i < 4; i++)
#pragma unroll
        for (int j = 0; j < 4; j++)
#pragma unroll
            for (int q = 0; q < 4; q++) acc[i][j][q] = 0.f;

    uint32_t a_base = smem_u32(sA) + ((wr * 64 + (lane & 15)) * 136 + (lane >> 4) * 8) * 2;
    int bn = (lane & 7) + (lane >> 4) * 8;
    uint32_t b_base = smem_u32(sB) + ((wc * 32 + bn) * 136 + ((lane >> 3) & 1) * 8) * 2;

    for (int kc = 0; kc < 2; kc++) {
        __syncthreads();
#pragma unroll
        for (int i = 0; i < 8; i++) {
            int idx = t + i * 256;
            int row = idx >> 4, c8 = (idx & 15) * 8;
            uint4 va = make_uint4(0, 0, 0, 0), vb = make_uint4(0, 0, 0, 0);
            if (r0 + row < Nn) va = *reinterpret_cast<const uint4*>(&g_vnP[(r0 + row) * 256 + kc * 128 + c8]);
            if (c0 + row < Nn) vb = *reinterpret_cast<const uint4*>(&g_vnP[(c0 + row) * 256 + kc * 128 + c8]);
            *reinterpret_cast<uint4*>(sA + row * 136 + c8) = va;
            *reinterpret_cast<uint4*>(sB + row * 136 + c8) = vb;
        }
        __syncthreads();
#pragma unroll
        for (int ks = 0; ks < 8; ks++) {
            uint32_t a[4][4], b[2][4];
#pragma unroll
            for (int mt = 0; mt < 4; mt++) LDSM4(a[mt], a_base + (mt * 16 * 136 + ks * 16) * 2);
#pragma unroll
            for (int n2 = 0; n2 < 2; n2++) LDSM4(b[n2], b_base + (n2 * 16 * 136 + ks * 16) * 2);
#pragma unroll
            for (int mt = 0; mt < 4; mt++)
#pragma unroll
                for (int nt = 0; nt < 4; nt++)
                    MMA_BF16(acc[mt][nt], a[mt], b[nt >> 1][(nt & 1) * 2], b[nt >> 1][(nt & 1) * 2 + 1]);
        }
    }

    int r_base = r0 + wr * 64 + (lane >> 2);
    int c_base = c0 + wc * 32 + (lane & 3) * 2;
#pragma unroll
    for (int mt = 0; mt < 4; mt++) {
        int r_lo = r_base + mt * 16, r_hi = r_lo + 8;
#pragma unroll
        for (int nt = 0; nt < 4; nt++) {
            int c = c_base + nt * 8;
            if (c < Nn) {
                if (r_lo < Nn)
                    *reinterpret_cast<float2*>(&g_raw[r_lo * LD + c]) =
                        make_float2(acc[mt][nt][0], acc[mt][nt][1]);
                if (r_hi < Nn)
                    *reinterpret_cast<float2*>(&g_raw[r_hi * LD + c]) =
                        make_float2(acc[mt][nt][2], acc[mt][nt][3]);
            }
        }
    }
}

// ---------------- fused w@v + asum: CTA = (m-chunk 128, r-tile 64), heads inside
// grid (16 m-chunks, 32 r-tiles), 256 threads (8 warps = 4r x 2d)
__global__ __launch_bounds__(256) void k_wx3(float* __restrict__ out) {
    extern __shared__ char smraw[];
    __nv_bfloat16* w_sm = reinterpret_cast<__nv_bfloat16*>(smraw);   // [64][136]
    __nv_bfloat16* sVh = w_sm + 64 * 136;                            // [32][136]
    __nv_bfloat16* sVl = sVh + 32 * 136;                             // [32][136]
    float* asum = reinterpret_cast<float*>(sVl + 32 * 136);          // [64][128]
    float* invS1 = asum + 64 * 128;                                  // [64]
    float* invS2 = invS1 + 64;                                       // [64]
    int t = threadIdx.x, lane = t & 31, wid = t >> 5;
    int wr = wid >> 1, wc = wid & 1;
    int m0 = blockIdx.x * 128, r0 = blockIdx.y * 64;

#pragma unroll
    for (int i = 0; i < 8; i++)
        *reinterpret_cast<float4*>(&asum[t * 4 + i * 1024]) = make_float4(0.f, 0.f, 0.f, 0.f);

    uint32_t a_base = smem_u32(w_sm) + ((wr * 16 + (lane & 15)) * 136 + (lane >> 4) * 8) * 2;
    int bn = (lane & 7) + (lane >> 4) * 8;
    uint32_t bh_base = smem_u32(sVh) + ((wc * 16 + bn) * 136 + ((lane >> 3) & 1) * 8) * 2;
    uint32_t bl_base = smem_u32(sVl) + ((wc * 16 + bn) * 136 + ((lane >> 3) & 1) * 8) * 2;

    for (int h = 0; h < Hh; h++) {
        __syncthreads();   // protect smem from previous head's MMA reads
        if (t < 64) {
            int r = r0 + t;
            invS1[t] = (r < Nn) ? 0.5f / g_S[0][h * Nn + r] : 0.f;
        } else if (t < 128) {
            int r = r0 + t - 64;
            invS2[t - 64] = (r < Nn) ? 0.5f / g_S[1][h * Nn + r] : 0.f;
        }
        __syncthreads();

        // vT tiles for this head (cols >= Nn are zero in gmem)
        const __nv_bfloat16* Vh = &g_vThi[h * 32 * LD];
        const __nv_bfloat16* Vl = &g_vTlo[h * 32 * LD];
#pragma unroll
        for (int i = 0; i < 2; i++) {
            int idx = t + i * 256;
            int row = idx >> 4, c8 = (idx & 15) * 8;
            *reinterpret_cast<uint4*>(sVh + row * 136 + c8) =
                *reinterpret_cast<const uint4*>(Vh + row * LD + m0 + c8);
            *reinterpret_cast<uint4*>(sVl + row * 136 + c8) =
                *reinterpret_cast<const uint4*>(Vl + row * LD + m0 + c8);
        }
        // w = mask(is1*E1 + is2*E2), accumulate asum (fp32), store bf16
        const __nv_bfloat16* E1 = &g_e[0][h][0];
        const __nv_bfloat16* E2 = &g_e[1][h][0];
#pragma unroll
        for (int i = 0; i < 4; i++) {
            int idx = t + i * 256;
            int rr = idx >> 4, m8 = (idx & 15) * 8;
            int r = r0 + rr;
            uint4 u1 = *reinterpret_cast<const uint4*>(E1 + (r0 + rr) * LD + m0 + m8);
            uint4 u2 = *reinterpret_cast<const uint4*>(E2 + (r0 + rr) * LD + m0 + m8);
            const __nv_bfloat162* p1 = reinterpret_cast<const __nv_bfloat162*>(&u1);
            const __nv_bfloat162* p2 = reinterpret_cast<const __nv_bfloat162*>(&u2);
            float is1 = invS1[rr], is2 = invS2[rr];
            int bs = (r / 10) * 10;
            float wv[8];
#pragma unroll
            for (int q2 = 0; q2 < 4; q2++) {
                float2 f1 = __bfloat1622float2(p1[q2]);
                float2 f2 = __bfloat1622float2(p2[q2]);
                wv[q2 * 2] = f1.x * is1 + f2.x * is2;
                wv[q2 * 2 + 1] = f1.y * is1 + f2.y * is2;
            }
#pragma unroll
            for (int q = 0; q < 8; q++) {
                int mm = m0 + m8 + q;
                if (mm >= bs && mm < bs + 9 && mm != r) wv[q] = 0.f;
            }
            float4* ap0 = reinterpret_cast<float4*>(&asum[rr * 128 + m8]);
            float4* ap1 = ap0 + 1;
            float4 a0 = *ap0, a1 = *ap1;
            a0.x += wv[0]; a0.y += wv[1]; a0.z += wv[2]; a0.w += wv[3];
            a1.x += wv[4]; a1.y += wv[5]; a1.z += wv[6]; a1.w += wv[7];
            *ap0 = a0; *ap1 = a1;
            __nv_bfloat16 wb[8];
#pragma unroll
            for (int q = 0; q < 8; q++) wb[q] = __float2bfloat16(wv[q]);
            *reinterpret_cast<uint4*>(w_sm + rr * 136 + m8) = *reinterpret_cast<const uint4*>(wb);
        }
        __syncthreads();

        float c[2][4];
#pragma unroll
        for (int nt = 0; nt < 2; nt++)
#pragma unroll
            for (int q = 0; q < 4; q++) c[nt][q] = 0.f;
#pragma unroll
        for (int ks = 0; ks < 8; ks++) {
            uint32_t a[4], bh[4], bl[4];
            LDSM4(a, a_base + ks * 32);
            LDSM4(bh, bh_base + ks * 32);
            LDSM4(bl, bl_base + ks * 32);
#pragma unroll
            for (int nt = 0; nt < 2; nt++) {
                MMA_BF16(c[nt], a, bh[nt * 2], bh[nt * 2 + 1]);
                MMA_BF16(c[nt], a, bl[nt * 2], bl[nt * 2 + 1]);
            }
        }
        int r_lo = r0 + wr * 16 + (lane >> 2);
        int r_hi = r_lo + 8;
#pragma unroll
        for (int nt = 0; nt < 2; nt++) {
            int d = wc * 16 + nt * 8 + (lane & 3) * 2;
            if (r_lo < Nn) {
                atomicAdd(&out[r_lo * 2 * Cc + h * Dd + d], c[nt][0]);
                atomicAdd(&out[r_lo * 2 * Cc + h * Dd + d + 1], c[nt][1]);
            }
            if (r_hi < Nn) {
                atomicAdd(&out[r_hi * 2 * Cc + h * Dd + d], c[nt][2]);
                atomicAdd(&out[r_hi * 2 * Cc + h * Dd + d + 1], c[nt][3]);
            }
        }
    }
    __syncthreads();
    // asum -> g_attn (exclusive (r,m) rectangle; plain stores)
#pragma unroll
    for (int i = 0; i < 4; i++) {
        int idx = t + i * 256;
        int rr = idx >> 4, m8 = (idx & 15) * 8;
        int r = r0 + rr;
        if (r < Nn) {
            *reinterpret_cast<float4*>(&g_attn[r * LD + m0 + m8]) =
                *reinterpret_cast<const float4*>(&asum[rr * 128 + m8]);
            *reinterpret_cast<float4*>(&g_attn[r * LD + m0 + m8 + 4]) =
                *reinterpret_cast<const float4*>(&asum[rr * 128 + m8 + 4]);
        }
    }
}

// ---------------- final sim: softmax of attn (pre-masked) + masked renorm ---
__global__ __launch_bounds__(256) void k_sim2(float* __restrict__ out) {
    __shared__ float e_row[Nn];
    __shared__ float red[2][8];
    int r = blockIdx.x, t = threadIdx.x;
    float se = 0.f, sm = 0.f;
    for (int m4 = t * 4; m4 < Nn; m4 += 1024) {
        float4 a = *reinterpret_cast<const float4*>(&g_attn[r * LD + m4]);
        float4 rw = *reinterpret_cast<const float4*>(&g_raw[r * LD + m4]);
        float e0 = __expf(a.x * 0.125f), e1 = __expf(a.y * 0.125f);
        float e2 = __expf(a.z * 0.125f), e3 = __expf(a.w * 0.125f);
        e_row[m4 + 0] = e0; e_row[m4 + 1] = e1;
        e_row[m4 + 2] = e2; e_row[m4 + 3] = e3;
        se += e0 + e1 + e2 + e3;
        if (rw.x > 6.0f) sm += e0;
        if (rw.y > 6.0f) sm += e1;
        if (rw.z > 6.0f) sm += e2;
        if (rw.w > 6.0f) sm += e3;
    }
#pragma unroll
    for (int off = 16; off; off >>= 1) {
        se += __shfl_xor_sync(0xffffffffu, se, off);
        sm += __shfl_xor_sync(0xffffffffu, sm, off);
    }
    int wid = t >> 5, lane = t & 31;
    if (!lane) { red[0][wid] = se; red[1][wid] = sm; }
    __syncthreads();
    if (t == 0) {
        float a = 0.f, b = 0.f;
        for (int i = 0; i < 8; i++) { a += red[0][i]; b += red[1][i]; }
        red[0][0] = a; red[1][0] = b;
    }
    __syncthreads();
    float S = red[0][0], Sm = red[1][0];
    float invS = 1.f / S;
    float invden = 1.f / (Sm * invS + 1e-8f);
    float* orow = &out[Nn * 2 * Cc + r * Nn];
    for (int m4 = t * 4; m4 < Nn; m4 += 1024) {
        float4 rw = *reinterpret_cast<const float4*>(&g_raw[r * LD + m4]);
        float4 o;
        o.x = (rw.x > 6.0f) ? e_row[m4 + 0] * invS * invden : 0.f;
        o.y = (rw.y > 6.0f) ? e_row[m4 + 1] * invS * invden : 0.f;
        o.z = (rw.z > 6.0f) ? e_row[m4 + 2] * invS * invden : 0.f;
        o.w = (rw.w > 6.0f) ? e_row[m4 + 3] * invS * invden : 0.f;
        *reinterpret_cast<float4*>(&orow[m4]) = o;
    }
}

// ---------------- launch ----------------------------------------------------
extern "C" void kernel_launch(void* const* d_in, const int* in_sizes, int n_in,
                              void* d_out, int out_size) {
    const float* x_cls = (const float*)d_in[0];
    const float* x_reg = (const float*)d_in[1];
    const float* W_cls = (const float*)d_in[2];
    const float* W_reg = (const float*)d_in[3];
    float* out = (float*)d_out;

    const int SM_T = 2 * 128 * 136 * 2;                               // 69632 B
    const int SM_W = (64 + 32 + 32) * 136 * 2 + (64 * 128 + 128) * 4; // 68096 B
    cudaFuncSetAttribute(k_logits_t, cudaFuncAttributeMaxDynamicSharedMemorySize, SM_T);
    cudaFuncSetAttribute(k_raw_t, cudaFuncAttributeMaxDynamicSharedMemorySize, SM_T);
    cudaFuncSetAttribute(k_wx3, cudaFuncAttributeMaxDynamicSharedMemorySize, SM_W);

    k_zeroS<<<(2 * Hh * Nn + 255) / 256, 256>>>();
    k_gemm<<<dim3(6, 16, 2), 256>>>(x_cls, W_cls, x_reg, W_reg);
    k_norm<<<Nn, 256>>>(out);
    k_vt<<<dim3(32, 8), 256>>>();
    k_logits_t<<<dim3(16, 16, 16), 256, SM_T>>>();
    k_raw_t<<<dim3(16, 16), 256, SM_T>>>();
    k_wx3<<<dim3(16, 32), 256, SM_W>>>(out);
    k_sim2<<<Nn, 256>>>(out);
}